// round 13
// baseline (speedup 1.0000x reference)
#include <cuda_runtime.h>
#include <cuda_bf16.h>
#include <cuda_fp16.h>
#include <cstdint>

#define NN 50000
#define EE 1600000

// ---------------- scratch (device globals) ----------------------------------
__device__ __half g_x[NN * 128];     // node features fp16 (px)
__device__ __half g_y[NN * 256];     // [Y0 | Y1] per node, fp16 messages
__device__ __half g_root[NN * 128];  // root projection fp16
__device__ uint32_t g_bt[155648];    // pre-packed fp16 weights (frag order)
__device__ int   g_cnt[2 * NN];
__device__ int   g_off[NN];
__device__ int   g_len[NN];
__device__ int   g_cur[NN];
__device__ int   g_list[EE];
__device__ float g_inv[2 * NN];
__device__ int   g_total;

// BT offsets in uint32 words (each word = half2)
#define BT_DES  0
#define BT_TWE  49152
#define BT_REL  98304         // + i*8192
#define BT_ROOT 131072        // + l*8192
#define BT_MLP1 147456

__device__ __forceinline__ float lrelu(float v) { return v > 0.f ? v : 0.01f * v; }

__device__ __forceinline__ uint32_t smem_u32(const void* p) {
    uint32_t a;
    asm("{ .reg .u64 t; cvta.to.shared.u64 t, %1; cvt.u32.u64 %0, t; }" : "=r"(a) : "l"(p));
    return a;
}

__device__ __forceinline__ void mma_f16(float c[4], const uint32_t a[4], const uint32_t b[2]) {
    asm volatile("mma.sync.aligned.m16n8k16.row.col.f32.f16.f16.f32 "
        "{%0,%1,%2,%3}, {%4,%5,%6,%7}, {%8,%9}, {%0,%1,%2,%3};"
        : "+f"(c[0]), "+f"(c[1]), "+f"(c[2]), "+f"(c[3])
        : "r"(a[0]), "r"(a[1]), "r"(a[2]), "r"(a[3]), "r"(b[0]), "r"(b[1]));
}

__device__ __forceinline__ void ldsm_x4(uint32_t r[4], uint32_t addr) {
    asm volatile("ldmatrix.sync.aligned.m8n8.x4.shared.b16 {%0,%1,%2,%3}, [%4];"
        : "=r"(r[0]), "=r"(r[1]), "=r"(r[2]), "=r"(r[3]) : "r"(addr));
}

__device__ __forceinline__ uint32_t h2u(__half2 h) { return *(uint32_t*)&h; }

// ---------------- device helpers ---------------------------------------------
__device__ __forceinline__ void dev_prep_b16(const float* __restrict__ src,
                                             uint32_t* __restrict__ dst, int K, int blk) {
    int w = blk * 256 + threadIdx.x;
    if (w >= K * 64) return;
    int kt = w >> 10;
    int within = w & 1023;
    int n8 = within >> 6;
    int rem = within & 63;
    int lane = rem >> 1;
    int j = rem & 1;
    int n = n8 * 8 + (lane >> 2);
    int k0 = kt * 16 + j * 8 + 2 * (lane & 3);
    __half2 h = __floats2half2_rn(src[(size_t)k0 * 128 + n], src[(size_t)(k0 + 1) * 128 + n]);
    dst[w] = h2u(h);
}

__device__ __forceinline__ void dev_hist(const int* __restrict__ ei,
                                         const int* __restrict__ et, int blk) {
    int e = blk * 256 + threadIdx.x;
    if (e < EE) atomicAdd(&g_cnt[et[e] * NN + ei[EE + e]], 1);
}

__device__ __forceinline__ void dev_fill(const int* __restrict__ ei,
                                         const int* __restrict__ et, int blk) {
    int e = blk * 256 + threadIdx.x;
    if (e < EE) {
        int pos = atomicAdd(&g_cur[ei[EE + e]], 1);
        g_list[pos] = (ei[e] << 1) | et[e];
    }
}

// A smem layout per ktile (1024 words): row r occupies words r*8..r*8+7;
// 16B chunk cc stored at position (cc ^ ((r>>2)&1)).
__device__ __forceinline__ uint32_t a_off16(int r, int c4) {
    return (uint32_t)(r * 8 + (((c4 >> 1) ^ ((r >> 2) & 1)) << 2) + (c4 & 1) * 2);
}

__device__ __forceinline__ uint32_t ldsm_row_off(int lane) {
    int r_local = (lane & 7) | (((lane >> 3) & 1) << 3);
    return (uint32_t)(r_local * 8 + ((((lane >> 4) & 1) ^ ((r_local >> 2) & 1)) << 2));
}

// ---------------- L1: zero counters + prep all weights -----------------------
__global__ void k_L1(const float* __restrict__ des_w, const float* __restrict__ tweet_w,
                     const float* __restrict__ rel_w, const float* __restrict__ root_w,
                     const float* __restrict__ mlp_w1, uint32_t* __restrict__ bt) {
    int bid = blockIdx.x;
    if (bid < 391) {
        int i = bid * 256 + threadIdx.x;
        if (i < 2 * NN) g_cnt[i] = 0;
        if (i == 0) g_total = 0;
        return;
    }
    int pb = bid - 391;
    if (pb < 192)       dev_prep_b16(des_w,   bt + BT_DES, 768, pb);
    else if (pb < 384)  dev_prep_b16(tweet_w, bt + BT_TWE, 768, pb - 192);
    else if (pb < 512)  { int i = (pb - 384) >> 5;
                          dev_prep_b16(rel_w + (size_t)i * 16384, bt + BT_REL + i * 8192, 128, (pb - 384) & 31); }
    else if (pb < 576)  { int l = (pb - 512) >> 5;
                          dev_prep_b16(root_w + (size_t)l * 16384, bt + BT_ROOT + l * 8192, 128, (pb - 512) & 31); }
    else                dev_prep_b16(mlp_w1, bt + BT_MLP1, 128, pb - 576);
}

// ---------------- L2 fused: des+numcat then tweets, writes px ∥ hist ----------
__global__ void __launch_bounds__(256, 2)
k_L2f(const float* __restrict__ des, const float* __restrict__ tweets,
      const uint32_t* __restrict__ bt, const float* __restrict__ des_b,
      const float* __restrict__ tweet_b,
      const float* __restrict__ numf, const float* __restrict__ catf,
      const float* __restrict__ num_w, const float* __restrict__ num_b,
      const float* __restrict__ cat_w, const float* __restrict__ cat_b,
      __half* __restrict__ px,
      const int* __restrict__ ei, const int* __restrict__ et) {
    __shared__ uint32_t As[2][1024];
    int bid = blockIdx.x;
    if (bid >= 391) { dev_hist(ei, et, bid - 391); return; }

    int tid  = threadIdx.x;
    int lane = tid & 31;
    int w    = tid >> 5;
    int wm   = w & 1;
    int wn   = w >> 1;
    int m0   = bid * 128;
    int grp  = lane >> 2;
    int q    = lane & 3;

    const int K = 768;
    const int nk = 48;

    float acc[4][4][4];
    uint4 ra4[2];
    uint32_t sbase = smem_u32(&As[0][0]);
    uint32_t lro4  = ldsm_row_off(lane) * 4;

    auto run_gemm = [&](const float* __restrict__ A, const uint32_t* __restrict__ Bp) {
        #pragma unroll
        for (int i = 0; i < 4; i++)
            #pragma unroll
            for (int j = 0; j < 4; j++)
                #pragma unroll
                for (int v = 0; v < 4; v++) acc[i][j][v] = 0.f;

        auto ldg_tile = [&](int kc) {
            #pragma unroll
            for (int u = 0; u < 2; u++) {
                int unit = tid + u * 256;
                int row  = unit >> 2;
                int c4   = unit & 3;
                int ar   = m0 + row; if (ar >= NN) ar = NN - 1;
                ra4[u] = *(const uint4*)&A[(size_t)ar * K + kc + c4 * 4];
            }
        };
        auto sts_tile = [&](int st) {
            #pragma unroll
            for (int u = 0; u < 2; u++) {
                int unit = tid + u * 256;
                const float* vf = (const float*)&ra4[u];
                __half2 h0 = __floats2half2_rn(vf[0], vf[1]);
                __half2 h1 = __floats2half2_rn(vf[2], vf[3]);
                *(uint2*)&As[st][a_off16(unit >> 2, unit & 3)] = make_uint2(h2u(h0), h2u(h1));
            }
        };
        auto compute = [&](int kt, int st) {
            const uint32_t* bbase = Bp + (size_t)kt * 1024;
            uint2 bf[4];
            #pragma unroll
            for (int nf = 0; nf < 4; nf++)
                bf[nf] = *(const uint2*)&bbase[(wn * 4 + nf) * 64 + lane * 2];
            uint32_t af[4][4];
            #pragma unroll
            for (int mf = 0; mf < 4; mf++)
                ldsm_x4(af[mf], sbase + (uint32_t)(st * 1024 + (wm * 4 + mf) * 128) * 4 + lro4);
            #pragma unroll
            for (int mf = 0; mf < 4; mf++)
                #pragma unroll
                for (int nf = 0; nf < 4; nf++)
                    mma_f16(acc[mf][nf], af[mf], (const uint32_t*)&bf[nf]);
        };

        ldg_tile(0);
        sts_tile(0);
        ldg_tile(16);
        __syncthreads();
        for (int kt = 0; kt < nk; kt++) {
            int st = kt & 1;
            compute(kt, st);
            if (kt + 1 < nk) {
                sts_tile(st ^ 1);
                if (kt + 2 < nk) ldg_tile((kt + 2) * 16);
            }
            __syncthreads();
        }
    };

    // ---- phase 1: des projection + num/cat, write px
    run_gemm(des, bt + BT_DES);
    #pragma unroll
    for (int mf = 0; mf < 4; mf++) {
        #pragma unroll
        for (int half = 0; half < 2; half++) {
            int row = m0 + wm * 64 + mf * 16 + grp + half * 8;
            if (row >= NN) continue;
            float nv[5], cv[6];
            #pragma unroll
            for (int k = 0; k < 5; k++) nv[k] = numf[row * 5 + k];
            #pragma unroll
            for (int k = 0; k < 6; k++) cv[k] = catf[row * 6 + k];
            #pragma unroll
            for (int nf = 0; nf < 4; nf++) {
                int col = wn * 32 + nf * 8 + q * 2;
                float o[2];
                #pragma unroll
                for (int v = 0; v < 2; v++) {
                    int c = col + v;
                    float dv = lrelu(acc[mf][nf][half * 2 + v] + des_b[c]);
                    float s = num_b[c];
                    #pragma unroll
                    for (int k = 0; k < 5; k++) s = fmaf(nv[k], num_w[k * 128 + c], s);
                    float t = cat_b[c];
                    #pragma unroll
                    for (int k = 0; k < 6; k++) t = fmaf(cv[k], cat_w[k * 128 + c], t);
                    o[v] = dv + lrelu(s) + lrelu(t);
                }
                *(__half2*)&px[(size_t)row * 128 + col] = __floats2half2_rn(o[0], o[1]);
            }
        }
    }
    __syncthreads();

    // ---- phase 2: tweets projection, accumulate into px
    run_gemm(tweets, bt + BT_TWE);
    #pragma unroll
    for (int mf = 0; mf < 4; mf++) {
        #pragma unroll
        for (int half = 0; half < 2; half++) {
            int row = m0 + wm * 64 + mf * 16 + grp + half * 8;
            if (row >= NN) continue;
            #pragma unroll
            for (int nf = 0; nf < 4; nf++) {
                int col = wn * 32 + nf * 8 + q * 2;
                __half2 old = *(const __half2*)&px[(size_t)row * 128 + col];
                float2 of = __half22float2(old);
                float v0 = of.x + lrelu(acc[mf][nf][half * 2 + 0] + tweet_b[col]);
                float v1 = of.y + lrelu(acc[mf][nf][half * 2 + 1] + tweet_b[col + 1]);
                *(__half2*)&px[(size_t)row * 128 + col] = __floats2half2_rn(v0, v1);
            }
        }
    }
}

// ---------------- assign (needs hist complete) --------------------------------
__global__ void k_assign() {
    int i = blockIdx.x * 256 + threadIdx.x;
    if (i >= NN) return;
    int c0 = g_cnt[i], c1 = g_cnt[NN + i];
    int deg = c0 + c1;
    int pos = atomicAdd(&g_total, deg);
    g_off[i] = pos;
    g_cur[i] = pos;
    g_len[i] = deg;
    g_inv[i]      = 1.0f / (c0 > 0 ? (float)c0 : 1.0f);
    g_inv[NN + i] = 1.0f / (c1 > 0 ? (float)c1 : 1.0f);
}

// ---------------- RGCN multi-B GEMM: fp16 A resident, fp16 outputs -----------
__global__ void __launch_bounds__(256, 2)
k_rgcn3(const __half* __restrict__ px,
        const uint32_t* __restrict__ b0p, const uint32_t* __restrict__ b1p,
        const uint32_t* __restrict__ b2p,
        __half* __restrict__ py, __half* __restrict__ proot,
        const int* __restrict__ ei, const int* __restrict__ et) {
    extern __shared__ uint32_t Asm[];
    int bid = blockIdx.x;
    if (bid >= 391) { dev_fill(ei, et, bid - 391); return; }

    int tid  = threadIdx.x;
    int lane = tid & 31;
    int w    = tid >> 5;
    int wm   = w & 1;
    int wn   = w >> 1;
    int m0   = bid * 128;
    int grp  = lane >> 2;
    int q    = lane & 3;

    #pragma unroll
    for (int kt = 0; kt < 8; kt++) {
        #pragma unroll
        for (int u = 0; u < 2; u++) {
            int unit = tid + u * 256;
            int row  = unit >> 2;
            int c4   = unit & 3;
            int ar   = m0 + row; if (ar >= NN) ar = NN - 1;
            uint2 ra = *(const uint2*)&px[(size_t)ar * 128 + kt * 16 + c4 * 4];
            *(uint2*)&Asm[kt * 1024 + a_off16(row, c4)] = ra;
        }
    }
    __syncthreads();

    const uint32_t* bsel[3] = { b0p, b1p, b2p };
    uint32_t sbase = smem_u32(Asm);
    uint32_t lro4  = ldsm_row_off(lane) * 4;

    #pragma unroll
    for (int b = 0; b < 3; b++) {
        const uint32_t* Bp = bsel[b];

        float acc[4][4][4];
        #pragma unroll
        for (int i = 0; i < 4; i++)
            #pragma unroll
            for (int j = 0; j < 4; j++)
                #pragma unroll
                for (int v = 0; v < 4; v++) acc[i][j][v] = 0.f;

        #pragma unroll
        for (int kt = 0; kt < 8; kt++) {
            const uint32_t* bbase = Bp + (size_t)kt * 1024;
            uint2 bf[4];
            #pragma unroll
            for (int nf = 0; nf < 4; nf++)
                bf[nf] = *(const uint2*)&bbase[(wn * 4 + nf) * 64 + lane * 2];
            uint32_t af[4][4];
            #pragma unroll
            for (int mf = 0; mf < 4; mf++)
                ldsm_x4(af[mf], sbase + (uint32_t)(kt * 1024 + (wm * 4 + mf) * 128) * 4 + lro4);
            #pragma unroll
            for (int mf = 0; mf < 4; mf++)
                #pragma unroll
                for (int nf = 0; nf < 4; nf++)
                    mma_f16(acc[mf][nf], af[mf], (const uint32_t*)&bf[nf]);
        }

        #pragma unroll
        for (int mf = 0; mf < 4; mf++) {
            int rbase = m0 + wm * 64 + mf * 16 + grp;
            #pragma unroll
            for (int half = 0; half < 2; half++) {
                int row = rbase + half * 8;
                if (row >= NN) continue;
                #pragma unroll
                for (int nf = 0; nf < 4; nf++) {
                    int col = wn * 32 + nf * 8 + q * 2;
                    __half2 hv = __floats2half2_rn(acc[mf][nf][half * 2 + 0],
                                                   acc[mf][nf][half * 2 + 1]);
                    if (b == 2)
                        *(__half2*)&proot[(size_t)row * 128 + col] = hv;
                    else
                        *(__half2*)&py[(size_t)row * 256 + b * 128 + col] = hv;
                }
            }
        }
    }
}

// ---------------- gather (fp16 in, fp32 accumulate, fp16 out) ----------------
__global__ void k_gather(const __half* __restrict__ y, const __half* __restrict__ root,
                         const float* __restrict__ bias, __half* __restrict__ xout) {
    int gw = (blockIdx.x * blockDim.x + threadIdx.x) >> 5;
    int lane = threadIdx.x & 31;
    if (gw >= NN) return;

    int beg = g_off[gw], len = g_len[gw];
    float a0[4] = {0.f, 0.f, 0.f, 0.f};
    float a1[4] = {0.f, 0.f, 0.f, 0.f};

    for (int j = 0; j < len; j++) {
        int p = __ldg(&g_list[beg + j]);
        const uint2 raw = *(const uint2*)(y + (size_t)(p >> 1) * 256 + (p & 1) * 128 + lane * 4);
        float2 f01 = __half22float2(*(const __half2*)&raw.x);
        float2 f23 = __half22float2(*(const __half2*)&raw.y);
        if (p & 1) { a1[0] += f01.x; a1[1] += f01.y; a1[2] += f23.x; a1[3] += f23.y; }
        else       { a0[0] += f01.x; a0[1] += f01.y; a0[2] += f23.x; a0[3] += f23.y; }
    }

    float i0 = g_inv[gw], i1 = g_inv[NN + gw];
    size_t base = (size_t)gw * 128 + lane * 4;
    uint2 ru = *(const uint2*)&root[base];
    float2 r01 = __half22float2(*(const __half2*)&ru.x);
    float2 r23 = __half22float2(*(const __half2*)&ru.y);
    float b0 = bias[lane * 4 + 0], b1 = bias[lane * 4 + 1];
    float b2 = bias[lane * 4 + 2], b3 = bias[lane * 4 + 3];

    float o0 = lrelu(r01.x + b0 + a0[0] * i0 + a1[0] * i1);
    float o1 = lrelu(r01.y + b1 + a0[1] * i0 + a1[1] * i1);
    float o2 = lrelu(r23.x + b2 + a0[2] * i0 + a1[2] * i1);
    float o3 = lrelu(r23.y + b3 + a0[3] * i0 + a1[3] * i1);
    __half2 h0 = __floats2half2_rn(o0, o1);
    __half2 h1 = __floats2half2_rn(o2, o3);
    *(uint2*)&xout[base] = make_uint2(h2u(h0), h2u(h1));
}

// ---------------- L8: MLP1 fp16 GEMM + fused 2-wide head ----------------------
__global__ void __launch_bounds__(256, 2)
k_mlp_head(const __half* __restrict__ A, const uint32_t* __restrict__ Bp,
           const float* __restrict__ b1, const float* __restrict__ w2,
           const float* __restrict__ b2, float* __restrict__ out) {
    __shared__ uint32_t As[2][1024];
    __shared__ float w2s[256];
    __shared__ float outs[128][2];

    int tid  = threadIdx.x;
    int lane = tid & 31;
    int w    = tid >> 5;
    int wm   = w & 1;
    int wn   = w >> 1;
    int m0   = blockIdx.x * 128;
    int grp  = lane >> 2;
    int q    = lane & 3;

    w2s[tid & 255] = w2[tid & 255];
    outs[tid >> 1][tid & 1] = 0.f;

    float acc[4][4][4];
    #pragma unroll
    for (int i = 0; i < 4; i++)
        #pragma unroll
        for (int j = 0; j < 4; j++)
            #pragma unroll
            for (int v = 0; v < 4; v++) acc[i][j][v] = 0.f;

    uint2 ra[2];
    const int K = 128;

    auto ldg_tile = [&](int kc) {
        #pragma unroll
        for (int u = 0; u < 2; u++) {
            int unit = tid + u * 256;
            int row  = unit >> 2;
            int c4   = unit & 3;
            int ar   = m0 + row; if (ar >= NN) ar = NN - 1;
            ra[u] = *(const uint2*)&A[(size_t)ar * K + kc + c4 * 4];
        }
    };
    auto sts_tile = [&](int st) {
        #pragma unroll
        for (int u = 0; u < 2; u++) {
            int unit = tid + u * 256;
            *(uint2*)&As[st][a_off16(unit >> 2, unit & 3)] = ra[u];
        }
    };
    uint32_t sbase = smem_u32(&As[0][0]);
    uint32_t lro4  = ldsm_row_off(lane) * 4;
    auto compute = [&](int kt, int st) {
        const uint32_t* bbase = Bp + (size_t)kt * 1024;
        uint2 bf[4];
        #pragma unroll
        for (int nf = 0; nf < 4; nf++)
            bf[nf] = *(const uint2*)&bbase[(wn * 4 + nf) * 64 + lane * 2];
        uint32_t af[4][4];
        #pragma unroll
        for (int mf = 0; mf < 4; mf++)
            ldsm_x4(af[mf], sbase + (uint32_t)(st * 1024 + (wm * 4 + mf) * 128) * 4 + lro4);
        #pragma unroll
        for (int mf = 0; mf < 4; mf++)
            #pragma unroll
            for (int nf = 0; nf < 4; nf++)
                mma_f16(acc[mf][nf], af[mf], (const uint32_t*)&bf[nf]);
    };

    int nk = K >> 4;   // 8
    ldg_tile(0);
    sts_tile(0);
    ldg_tile(16);
    __syncthreads();
    for (int kt = 0; kt < nk; kt++) {
        int st = kt & 1;
        compute(kt, st);
        if (kt + 1 < nk) {
            sts_tile(st ^ 1);
            if (kt + 2 < nk) ldg_tile((kt + 2) * 16);
        }
        __syncthreads();
    }

    // head: out[row] = relu(acc + b1) @ w2 + b2
    #pragma unroll
    for (int mf = 0; mf < 4; mf++) {
        #pragma unroll
        for (int half = 0; half < 2; half++) {
            int rl = wm * 64 + mf * 16 + grp + half * 8;
            float p0 = 0.f, p1 = 0.f;
            #pragma unroll
            for (int nf = 0; nf < 4; nf++) {
                #pragma unroll
                for (int v = 0; v < 2; v++) {
                    int col = wn * 32 + nf * 8 + q * 2 + v;
                    float h = fmaxf(acc[mf][nf][half * 2 + v] + b1[col], 0.f);
                    p0 = fmaf(h, w2s[col * 2 + 0], p0);
                    p1 = fmaf(h, w2s[col * 2 + 1], p1);
                }
            }
            p0 += __shfl_xor_sync(0xFFFFFFFFu, p0, 1);
            p0 += __shfl_xor_sync(0xFFFFFFFFu, p0, 2);
            p1 += __shfl_xor_sync(0xFFFFFFFFu, p1, 1);
            p1 += __shfl_xor_sync(0xFFFFFFFFu, p1, 2);
            if (q == 0) {
                atomicAdd(&outs[rl][0], p0);
                atomicAdd(&outs[rl][1], p1);
            }
        }
    }
    __syncthreads();
    int r = tid >> 1, c = tid & 1;
    int row = m0 + r;
    if (row < NN) out[row * 2 + c] = outs[r][c] + b2[c];
}

// ---------------- launch -------------------------------------------------------
#define RGCN_SMEM 32768

extern "C" void kernel_launch(void* const* d_in, const int* in_sizes, int n_in,
                              void* d_out, int out_size) {
    const float* des     = (const float*)d_in[0];
    const float* tweets  = (const float*)d_in[1];
    const float* numf    = (const float*)d_in[2];
    const float* catf    = (const float*)d_in[3];
    const int*   ei      = (const int*)d_in[4];
    const int*   et      = (const int*)d_in[5];
    const float* des_w   = (const float*)d_in[6];
    const float* des_b   = (const float*)d_in[7];
    const float* tweet_w = (const float*)d_in[8];
    const float* tweet_b = (const float*)d_in[9];
    const float* num_w   = (const float*)d_in[10];
    const float* num_b   = (const float*)d_in[11];
    const float* cat_w   = (const float*)d_in[12];
    const float* cat_b   = (const float*)d_in[13];
    const float* rel_w   = (const float*)d_in[14];
    const float* root_w  = (const float*)d_in[15];
    const float* rgcn_b  = (const float*)d_in[16];
    const float* mlp_w1  = (const float*)d_in[17];
    const float* mlp_b1  = (const float*)d_in[18];
    const float* mlp_w2  = (const float*)d_in[19];
    const float* mlp_b2  = (const float*)d_in[20];
    float* out = (float*)d_out;

    __half *px, *py, *proot;
    uint32_t *pbt;
    cudaGetSymbolAddress((void**)&px,    g_x);
    cudaGetSymbolAddress((void**)&py,    g_y);
    cudaGetSymbolAddress((void**)&proot, g_root);
    cudaGetSymbolAddress((void**)&pbt,   g_bt);

    cudaFuncSetAttribute(k_rgcn3, cudaFuncAttributeMaxDynamicSharedMemorySize, RGCN_SMEM);

    // L1: zero counters ∥ prep all weights (fp16 frag order)
    k_L1<<<391 + 608, 256>>>(des_w, tweet_w, rel_w, root_w, mlp_w1, pbt);

    // L2: fused des+numcat+tweets projections → px ∥ hist
    k_L2f<<<391 + 6250, 256>>>(des, tweets, pbt, des_b, tweet_b,
                               numf, catf, num_w, num_b, cat_w, cat_b,
                               px, ei, et);

    // assign (hist must be complete)
    k_assign<<<196, 256>>>();

    // L4: RGCN layer 0 ∥ fill
    k_rgcn3<<<391 + 6250, 256, RGCN_SMEM>>>(px, pbt + BT_REL, pbt + BT_REL + 8192,
                                            pbt + BT_ROOT, py, proot, ei, et);
    k_gather<<<(NN * 32) / 256, 256>>>(py, proot, rgcn_b, px);

    // L6: RGCN layer 1
    k_rgcn3<<<391, 256, RGCN_SMEM>>>(px, pbt + BT_REL + 2 * 8192, pbt + BT_REL + 3 * 8192,
                                     pbt + BT_ROOT + 8192, py, proot, ei, et);
    k_gather<<<(NN * 32) / 256, 256>>>(py, proot, rgcn_b + 128, px);

    // L8: MLP1 + fused head
    k_mlp_head<<<391, 256>>>(px, pbt + BT_MLP1, mlp_b1, mlp_w2, mlp_b2, out);
}

// round 14
// speedup vs baseline: 1.0919x; 1.0919x over previous
#include <cuda_runtime.h>
#include <cuda_bf16.h>
#include <cuda_fp16.h>
#include <cstdint>

#define NN 50000
#define EE 1600000

// ---------------- scratch (device globals) ----------------------------------
__device__ __half g_x[NN * 128];     // node features fp16 (px)
__device__ __half g_h[NN * 128];     // tweets projection fp16
__device__ __half g_y[NN * 256];     // [Y0 | Y1] per node, fp16 messages
__device__ __half g_root[NN * 128];  // root projection fp16
__device__ uint32_t g_bt[155648];    // pre-packed fp16 weights (frag order)
__device__ int   g_cnt[2 * NN];
__device__ int   g_off[NN];
__device__ int   g_len[NN];
__device__ int   g_cur[NN];
__device__ int   g_list[EE];
__device__ float g_inv[2 * NN];
__device__ int   g_total;

// BT offsets in uint32 words (each word = half2)
#define BT_DES  0
#define BT_TWE  49152
#define BT_REL  98304         // + i*8192
#define BT_ROOT 131072        // + l*8192
#define BT_MLP1 147456

__device__ __forceinline__ float lrelu(float v) { return v > 0.f ? v : 0.01f * v; }

__device__ __forceinline__ uint32_t smem_u32(const void* p) {
    uint32_t a;
    asm("{ .reg .u64 t; cvta.to.shared.u64 t, %1; cvt.u32.u64 %0, t; }" : "=r"(a) : "l"(p));
    return a;
}

__device__ __forceinline__ void mma_f16(float c[4], const uint32_t a[4], const uint32_t b[2]) {
    asm volatile("mma.sync.aligned.m16n8k16.row.col.f32.f16.f16.f32 "
        "{%0,%1,%2,%3}, {%4,%5,%6,%7}, {%8,%9}, {%0,%1,%2,%3};"
        : "+f"(c[0]), "+f"(c[1]), "+f"(c[2]), "+f"(c[3])
        : "r"(a[0]), "r"(a[1]), "r"(a[2]), "r"(a[3]), "r"(b[0]), "r"(b[1]));
}

__device__ __forceinline__ void ldsm_x4(uint32_t r[4], uint32_t addr) {
    asm volatile("ldmatrix.sync.aligned.m8n8.x4.shared.b16 {%0,%1,%2,%3}, [%4];"
        : "=r"(r[0]), "=r"(r[1]), "=r"(r[2]), "=r"(r[3]) : "r"(addr));
}

__device__ __forceinline__ uint32_t h2u(__half2 h) { return *(uint32_t*)&h; }

// ---------------- device helpers ---------------------------------------------
__device__ __forceinline__ void dev_prep_b16(const float* __restrict__ src,
                                             uint32_t* __restrict__ dst, int K, int blk) {
    int w = blk * 256 + threadIdx.x;
    if (w >= K * 64) return;
    int kt = w >> 10;
    int within = w & 1023;
    int n8 = within >> 6;
    int rem = within & 63;
    int lane = rem >> 1;
    int j = rem & 1;
    int n = n8 * 8 + (lane >> 2);
    int k0 = kt * 16 + j * 8 + 2 * (lane & 3);
    __half2 h = __floats2half2_rn(src[(size_t)k0 * 128 + n], src[(size_t)(k0 + 1) * 128 + n]);
    dst[w] = h2u(h);
}

__device__ __forceinline__ void dev_hist(const int* __restrict__ ei,
                                         const int* __restrict__ et, int blk) {
    int e = blk * 256 + threadIdx.x;
    if (e < EE) atomicAdd(&g_cnt[et[e] * NN + ei[EE + e]], 1);
}

__device__ __forceinline__ void dev_assign(int blk) {
    int i = blk * 256 + threadIdx.x;
    if (i >= NN) return;
    int c0 = g_cnt[i], c1 = g_cnt[NN + i];
    int deg = c0 + c1;
    int pos = atomicAdd(&g_total, deg);
    g_off[i] = pos;
    g_cur[i] = pos;
    g_len[i] = deg;
    g_inv[i]      = 1.0f / (c0 > 0 ? (float)c0 : 1.0f);
    g_inv[NN + i] = 1.0f / (c1 > 0 ? (float)c1 : 1.0f);
}

__device__ __forceinline__ void dev_fill(const int* __restrict__ ei,
                                         const int* __restrict__ et, int blk) {
    int e = blk * 256 + threadIdx.x;
    if (e < EE) {
        int pos = atomicAdd(&g_cur[ei[EE + e]], 1);
        g_list[pos] = (ei[e] << 1) | et[e];
    }
}

// A smem layout per ktile (1024 words): row r occupies words r*8..r*8+7;
// 16B chunk cc stored at position (cc ^ ((r>>2)&1)).
__device__ __forceinline__ uint32_t a_off16(int r, int c4) {
    return (uint32_t)(r * 8 + (((c4 >> 1) ^ ((r >> 2) & 1)) << 2) + (c4 & 1) * 2);
}

__device__ __forceinline__ uint32_t ldsm_row_off(int lane) {
    int r_local = (lane & 7) | (((lane >> 3) & 1) << 3);
    return (uint32_t)(r_local * 8 + ((((lane >> 4) & 1) ^ ((r_local >> 2) & 1)) << 2));
}

// ---------------- fp16 GEMM body ----------------------------------------------
template <int ACT, bool AHALF, bool OUTHALF>
__device__ __forceinline__ void gemm_body16(
    const void* __restrict__ Av, const uint32_t* __restrict__ Bp,
    const float* __restrict__ bias, void* __restrict__ Cv,
    int M, int K, int ldc, int bidx,
    uint32_t (*As)[1024]) {

    int tid  = threadIdx.x;
    int lane = tid & 31;
    int w    = tid >> 5;
    int wm   = w & 1;
    int wn   = w >> 1;
    int m0   = bidx * 128;
    int grp  = lane >> 2;
    int q    = lane & 3;

    float acc[4][4][4];
    #pragma unroll
    for (int i = 0; i < 4; i++)
        #pragma unroll
        for (int j = 0; j < 4; j++)
            #pragma unroll
            for (int v = 0; v < 4; v++) acc[i][j][v] = 0.f;

    uint4 ra4[2];
    uint2 ra2[2];

    auto ldg_tile = [&](int kc) {
        #pragma unroll
        for (int u = 0; u < 2; u++) {
            int unit = tid + u * 256;
            int row  = unit >> 2;
            int c4   = unit & 3;
            int ar   = m0 + row; if (ar >= M) ar = M - 1;
            if (AHALF) {
                const __half* Ah = (const __half*)Av;
                ra2[u] = *(const uint2*)&Ah[(size_t)ar * K + kc + c4 * 4];
            } else {
                const float* Af = (const float*)Av;
                ra4[u] = *(const uint4*)&Af[(size_t)ar * K + kc + c4 * 4];
            }
        }
    };

    auto sts_tile = [&](int st) {
        #pragma unroll
        for (int u = 0; u < 2; u++) {
            int unit = tid + u * 256;
            uint32_t off = a_off16(unit >> 2, unit & 3);
            if (AHALF) {
                *(uint2*)&As[st][off] = ra2[u];
            } else {
                const float* vf = (const float*)&ra4[u];
                __half2 h0 = __floats2half2_rn(vf[0], vf[1]);
                __half2 h1 = __floats2half2_rn(vf[2], vf[3]);
                *(uint2*)&As[st][off] = make_uint2(h2u(h0), h2u(h1));
            }
        }
    };

    uint32_t sbase = smem_u32(&As[0][0]);
    uint32_t lro4  = ldsm_row_off(lane) * 4;

    auto compute = [&](int kt, int st) {
        const uint32_t* bbase = Bp + (size_t)kt * 1024;
        uint2 bf[4];
        #pragma unroll
        for (int nf = 0; nf < 4; nf++)
            bf[nf] = *(const uint2*)&bbase[(wn * 4 + nf) * 64 + lane * 2];
        uint32_t af[4][4];
        #pragma unroll
        for (int mf = 0; mf < 4; mf++)
            ldsm_x4(af[mf], sbase + (uint32_t)(st * 1024 + (wm * 4 + mf) * 128) * 4 + lro4);
        #pragma unroll
        for (int mf = 0; mf < 4; mf++)
            #pragma unroll
            for (int nf = 0; nf < 4; nf++)
                mma_f16(acc[mf][nf], af[mf], (const uint32_t*)&bf[nf]);
    };

    int nk = K >> 4;
    ldg_tile(0);
    sts_tile(0);
    if (nk > 1) ldg_tile(16);
    __syncthreads();

    for (int kt = 0; kt < nk; kt++) {
        int st = kt & 1;
        compute(kt, st);
        if (kt + 1 < nk) {
            sts_tile(st ^ 1);
            if (kt + 2 < nk) ldg_tile((kt + 2) * 16);
        }
        __syncthreads();
    }

    #pragma unroll
    for (int mf = 0; mf < 4; mf++) {
        int rbase = m0 + wm * 64 + mf * 16 + grp;
        #pragma unroll
        for (int half = 0; half < 2; half++) {
            int row = rbase + half * 8;
            if (row >= M) continue;
            #pragma unroll
            for (int nf = 0; nf < 4; nf++) {
                int col = wn * 32 + nf * 8 + q * 2;
                float v0 = acc[mf][nf][half * 2 + 0];
                float v1 = acc[mf][nf][half * 2 + 1];
                if (bias) { v0 += bias[col]; v1 += bias[col + 1]; }
                if (ACT == 1) { v0 = lrelu(v0); v1 = lrelu(v1); }
                else if (ACT == 2) { v0 = fmaxf(v0, 0.f); v1 = fmaxf(v1, 0.f); }
                if (OUTHALF) {
                    __half* Ch = (__half*)Cv;
                    *(__half2*)&Ch[(size_t)row * ldc + col] = __floats2half2_rn(v0, v1);
                } else {
                    float* Cf = (float*)Cv;
                    Cf[(size_t)row * ldc + col]     = v0;
                    Cf[(size_t)row * ldc + col + 1] = v1;
                }
            }
        }
    }
}

// ---------------- L1: prep all weights ∥ hist (counters pre-zeroed) ----------
__global__ void k_L1(const float* __restrict__ des_w, const float* __restrict__ tweet_w,
                     const float* __restrict__ rel_w, const float* __restrict__ root_w,
                     const float* __restrict__ mlp_w1, uint32_t* __restrict__ bt,
                     const int* __restrict__ ei, const int* __restrict__ et) {
    int bid = blockIdx.x;
    if (bid >= 640) { dev_hist(ei, et, bid - 640); return; }
    int pb = bid;
    if (pb < 192)       dev_prep_b16(des_w,   bt + BT_DES, 768, pb);
    else if (pb < 384)  dev_prep_b16(tweet_w, bt + BT_TWE, 768, pb - 192);
    else if (pb < 512)  { int i = (pb - 384) >> 5;
                          dev_prep_b16(rel_w + (size_t)i * 16384, bt + BT_REL + i * 8192, 128, (pb - 384) & 31); }
    else if (pb < 576)  { int l = (pb - 512) >> 5;
                          dev_prep_b16(root_w + (size_t)l * 16384, bt + BT_ROOT + l * 8192, 128, (pb - 512) & 31); }
    else if (pb < 608)  dev_prep_b16(mlp_w1, bt + BT_MLP1, 128, pb - 576);
    // 608..639: idle padding (keeps hist offset round)
}

// ---------------- L2: des-GEMM ∥ tweets-GEMM ∥ assign -------------------------
__global__ void __launch_bounds__(256, 2)
k_L2(const float* __restrict__ des, const float* __restrict__ tweets,
     const uint32_t* __restrict__ bt, const float* __restrict__ des_b,
     const float* __restrict__ tweet_b, __half* __restrict__ ox,
     __half* __restrict__ oh) {
    __shared__ uint32_t As[2][1024];
    int bid = blockIdx.x;
    if (bid < 391)
        gemm_body16<1, false, true>(des, bt + BT_DES, des_b, ox, NN, 768, 128, bid, As);
    else if (bid < 782)
        gemm_body16<1, false, true>(tweets, bt + BT_TWE, tweet_b, oh, NN, 768, 128, bid - 391, As);
    else
        dev_assign(bid - 782);
}

// ---------------- L3: combine (fp16 in/out) ∥ fill -----------------------------
__global__ void k_L3(const float* __restrict__ numf, const float* __restrict__ catf,
                     const float* __restrict__ num_w, const float* __restrict__ num_b,
                     const float* __restrict__ cat_w, const float* __restrict__ cat_b,
                     const __half* __restrict__ gx, const __half* __restrict__ gh,
                     __half* __restrict__ px,
                     const int* __restrict__ ei, const int* __restrict__ et) {
    int bid = blockIdx.x;
    if (bid >= 6250) { dev_fill(ei, et, bid - 6250); return; }
    int wid  = threadIdx.x >> 5;
    int lane = threadIdx.x & 31;
    int row  = bid * 8 + wid;
    if (row >= NN) return;

    float nv[5], cv[6];
    #pragma unroll
    for (int k = 0; k < 5; k++) nv[k] = numf[row * 5 + k];
    #pragma unroll
    for (int k = 0; k < 6; k++) cv[k] = catf[row * 6 + k];

    size_t base = (size_t)row * 128 + lane * 4;
    uint2 au = *(const uint2*)&gx[base];
    uint2 bu = *(const uint2*)&gh[base];
    float2 a01 = __half22float2(*(const __half2*)&au.x);
    float2 a23 = __half22float2(*(const __half2*)&au.y);
    float2 b01 = __half22float2(*(const __half2*)&bu.x);
    float2 b23 = __half22float2(*(const __half2*)&bu.y);
    float af[4] = {a01.x, a01.y, a23.x, a23.y};
    float bf[4] = {b01.x, b01.y, b23.x, b23.y};

    float o[4];
    #pragma unroll
    for (int u = 0; u < 4; u++) {
        int col = lane * 4 + u;
        float s = num_b[col];
        #pragma unroll
        for (int k = 0; k < 5; k++) s = fmaf(nv[k], num_w[k * 128 + col], s);
        float t = cat_b[col];
        #pragma unroll
        for (int k = 0; k < 6; k++) t = fmaf(cv[k], cat_w[k * 128 + col], t);
        o[u] = af[u] + bf[u] + lrelu(s) + lrelu(t);
    }
    __half2 h0 = __floats2half2_rn(o[0], o[1]);
    __half2 h1 = __floats2half2_rn(o[2], o[3]);
    *(uint2*)&px[base] = make_uint2(h2u(h0), h2u(h1));
}

// ---------------- RGCN multi-B GEMM: fp16 A resident, fp16 outputs -----------
__global__ void __launch_bounds__(256, 2)
k_rgcn3(const __half* __restrict__ px,
        const uint32_t* __restrict__ b0p, const uint32_t* __restrict__ b1p,
        const uint32_t* __restrict__ b2p,
        __half* __restrict__ py, __half* __restrict__ proot) {
    extern __shared__ uint32_t Asm[];
    int bid = blockIdx.x;

    int tid  = threadIdx.x;
    int lane = tid & 31;
    int w    = tid >> 5;
    int wm   = w & 1;
    int wn   = w >> 1;
    int m0   = bid * 128;
    int grp  = lane >> 2;
    int q    = lane & 3;

    #pragma unroll
    for (int kt = 0; kt < 8; kt++) {
        #pragma unroll
        for (int u = 0; u < 2; u++) {
            int unit = tid + u * 256;
            int row  = unit >> 2;
            int c4   = unit & 3;
            int ar   = m0 + row; if (ar >= NN) ar = NN - 1;
            uint2 ra = *(const uint2*)&px[(size_t)ar * 128 + kt * 16 + c4 * 4];
            *(uint2*)&Asm[kt * 1024 + a_off16(row, c4)] = ra;
        }
    }
    __syncthreads();

    const uint32_t* bsel[3] = { b0p, b1p, b2p };
    uint32_t sbase = smem_u32(Asm);
    uint32_t lro4  = ldsm_row_off(lane) * 4;

    #pragma unroll
    for (int b = 0; b < 3; b++) {
        const uint32_t* Bp = bsel[b];

        float acc[4][4][4];
        #pragma unroll
        for (int i = 0; i < 4; i++)
            #pragma unroll
            for (int j = 0; j < 4; j++)
                #pragma unroll
                for (int v = 0; v < 4; v++) acc[i][j][v] = 0.f;

        #pragma unroll
        for (int kt = 0; kt < 8; kt++) {
            const uint32_t* bbase = Bp + (size_t)kt * 1024;
            uint2 bf[4];
            #pragma unroll
            for (int nf = 0; nf < 4; nf++)
                bf[nf] = *(const uint2*)&bbase[(wn * 4 + nf) * 64 + lane * 2];
            uint32_t af[4][4];
            #pragma unroll
            for (int mf = 0; mf < 4; mf++)
                ldsm_x4(af[mf], sbase + (uint32_t)(kt * 1024 + (wm * 4 + mf) * 128) * 4 + lro4);
            #pragma unroll
            for (int mf = 0; mf < 4; mf++)
                #pragma unroll
                for (int nf = 0; nf < 4; nf++)
                    mma_f16(acc[mf][nf], af[mf], (const uint32_t*)&bf[nf]);
        }

        #pragma unroll
        for (int mf = 0; mf < 4; mf++) {
            int rbase = m0 + wm * 64 + mf * 16 + grp;
            #pragma unroll
            for (int half = 0; half < 2; half++) {
                int row = rbase + half * 8;
                if (row >= NN) continue;
                #pragma unroll
                for (int nf = 0; nf < 4; nf++) {
                    int col = wn * 32 + nf * 8 + q * 2;
                    __half2 hv = __floats2half2_rn(acc[mf][nf][half * 2 + 0],
                                                   acc[mf][nf][half * 2 + 1]);
                    if (b == 2)
                        *(__half2*)&proot[(size_t)row * 128 + col] = hv;
                    else
                        *(__half2*)&py[(size_t)row * 256 + b * 128 + col] = hv;
                }
            }
        }
    }
}

// ---------------- gather (fp16 in, fp32 accumulate, fp16 out) ----------------
__global__ void k_gather(const __half* __restrict__ y, const __half* __restrict__ root,
                         const float* __restrict__ bias, __half* __restrict__ xout) {
    int gw = (blockIdx.x * blockDim.x + threadIdx.x) >> 5;
    int lane = threadIdx.x & 31;
    if (gw >= NN) return;

    int beg = g_off[gw], len = g_len[gw];
    float a0[4] = {0.f, 0.f, 0.f, 0.f};
    float a1[4] = {0.f, 0.f, 0.f, 0.f};

    for (int j = 0; j < len; j++) {
        int p = __ldg(&g_list[beg + j]);
        const uint2 raw = *(const uint2*)(y + (size_t)(p >> 1) * 256 + (p & 1) * 128 + lane * 4);
        float2 f01 = __half22float2(*(const __half2*)&raw.x);
        float2 f23 = __half22float2(*(const __half2*)&raw.y);
        if (p & 1) { a1[0] += f01.x; a1[1] += f01.y; a1[2] += f23.x; a1[3] += f23.y; }
        else       { a0[0] += f01.x; a0[1] += f01.y; a0[2] += f23.x; a0[3] += f23.y; }
    }

    float i0 = g_inv[gw], i1 = g_inv[NN + gw];
    size_t base = (size_t)gw * 128 + lane * 4;
    uint2 ru = *(const uint2*)&root[base];
    float2 r01 = __half22float2(*(const __half2*)&ru.x);
    float2 r23 = __half22float2(*(const __half2*)&ru.y);
    float b0 = bias[lane * 4 + 0], b1 = bias[lane * 4 + 1];
    float b2 = bias[lane * 4 + 2], b3 = bias[lane * 4 + 3];

    float o0 = lrelu(r01.x + b0 + a0[0] * i0 + a1[0] * i1);
    float o1 = lrelu(r01.y + b1 + a0[1] * i0 + a1[1] * i1);
    float o2 = lrelu(r23.x + b2 + a0[2] * i0 + a1[2] * i1);
    float o3 = lrelu(r23.y + b3 + a0[3] * i0 + a1[3] * i1);
    __half2 h0 = __floats2half2_rn(o0, o1);
    __half2 h1 = __floats2half2_rn(o2, o3);
    *(uint2*)&xout[base] = make_uint2(h2u(h0), h2u(h1));
}

// ---------------- L8: MLP1 fp16 GEMM + fused 2-wide head ----------------------
__global__ void __launch_bounds__(256, 2)
k_mlp_head(const __half* __restrict__ A, const uint32_t* __restrict__ Bp,
           const float* __restrict__ b1, const float* __restrict__ w2,
           const float* __restrict__ b2, float* __restrict__ out) {
    __shared__ uint32_t As[2][1024];
    __shared__ float w2s[256];
    __shared__ float outs[128][2];

    int tid  = threadIdx.x;
    int lane = tid & 31;
    int w    = tid >> 5;
    int wm   = w & 1;
    int wn   = w >> 1;
    int m0   = blockIdx.x * 128;
    int grp  = lane >> 2;
    int q    = lane & 3;

    w2s[tid & 255] = w2[tid & 255];
    outs[tid >> 1][tid & 1] = 0.f;

    float acc[4][4][4];
    #pragma unroll
    for (int i = 0; i < 4; i++)
        #pragma unroll
        for (int j = 0; j < 4; j++)
            #pragma unroll
            for (int v = 0; v < 4; v++) acc[i][j][v] = 0.f;

    uint2 ra[2];
    const int K = 128;

    auto ldg_tile = [&](int kc) {
        #pragma unroll
        for (int u = 0; u < 2; u++) {
            int unit = tid + u * 256;
            int row  = unit >> 2;
            int c4   = unit & 3;
            int ar   = m0 + row; if (ar >= NN) ar = NN - 1;
            ra[u] = *(const uint2*)&A[(size_t)ar * K + kc + c4 * 4];
        }
    };
    auto sts_tile = [&](int st) {
        #pragma unroll
        for (int u = 0; u < 2; u++) {
            int unit = tid + u * 256;
            *(uint2*)&As[st][a_off16(unit >> 2, unit & 3)] = ra[u];
        }
    };
    uint32_t sbase = smem_u32(&As[0][0]);
    uint32_t lro4  = ldsm_row_off(lane) * 4;
    auto compute = [&](int kt, int st) {
        const uint32_t* bbase = Bp + (size_t)kt * 1024;
        uint2 bf[4];
        #pragma unroll
        for (int nf = 0; nf < 4; nf++)
            bf[nf] = *(const uint2*)&bbase[(wn * 4 + nf) * 64 + lane * 2];
        uint32_t af[4][4];
        #pragma unroll
        for (int mf = 0; mf < 4; mf++)
            ldsm_x4(af[mf], sbase + (uint32_t)(st * 1024 + (wm * 4 + mf) * 128) * 4 + lro4);
        #pragma unroll
        for (int mf = 0; mf < 4; mf++)
            #pragma unroll
            for (int nf = 0; nf < 4; nf++)
                mma_f16(acc[mf][nf], af[mf], (const uint32_t*)&bf[nf]);
    };

    int nk = K >> 4;   // 8
    ldg_tile(0);
    sts_tile(0);
    ldg_tile(16);
    __syncthreads();
    for (int kt = 0; kt < nk; kt++) {
        int st = kt & 1;
        compute(kt, st);
        if (kt + 1 < nk) {
            sts_tile(st ^ 1);
            if (kt + 2 < nk) ldg_tile((kt + 2) * 16);
        }
        __syncthreads();
    }

    // head: out[row] = relu(acc + b1) @ w2 + b2
    #pragma unroll
    for (int mf = 0; mf < 4; mf++) {
        #pragma unroll
        for (int half = 0; half < 2; half++) {
            int rl = wm * 64 + mf * 16 + grp + half * 8;
            float p0 = 0.f, p1 = 0.f;
            #pragma unroll
            for (int nf = 0; nf < 4; nf++) {
                #pragma unroll
                for (int v = 0; v < 2; v++) {
                    int col = wn * 32 + nf * 8 + q * 2 + v;
                    float h = fmaxf(acc[mf][nf][half * 2 + v] + b1[col], 0.f);
                    p0 = fmaf(h, w2s[col * 2 + 0], p0);
                    p1 = fmaf(h, w2s[col * 2 + 1], p1);
                }
            }
            p0 += __shfl_xor_sync(0xFFFFFFFFu, p0, 1);
            p0 += __shfl_xor_sync(0xFFFFFFFFu, p0, 2);
            p1 += __shfl_xor_sync(0xFFFFFFFFu, p1, 1);
            p1 += __shfl_xor_sync(0xFFFFFFFFu, p1, 2);
            if (q == 0) {
                atomicAdd(&outs[rl][0], p0);
                atomicAdd(&outs[rl][1], p1);
            }
        }
    }
    __syncthreads();
    int r = tid >> 1, c = tid & 1;
    int row = m0 + r;
    if (row < NN) out[row * 2 + c] = outs[r][c] + b2[c];
}

// ---------------- launch -------------------------------------------------------
#define RGCN_SMEM 32768

extern "C" void kernel_launch(void* const* d_in, const int* in_sizes, int n_in,
                              void* d_out, int out_size) {
    const float* des     = (const float*)d_in[0];
    const float* tweets  = (const float*)d_in[1];
    const float* numf    = (const float*)d_in[2];
    const float* catf    = (const float*)d_in[3];
    const int*   ei      = (const int*)d_in[4];
    const int*   et      = (const int*)d_in[5];
    const float* des_w   = (const float*)d_in[6];
    const float* des_b   = (const float*)d_in[7];
    const float* tweet_w = (const float*)d_in[8];
    const float* tweet_b = (const float*)d_in[9];
    const float* num_w   = (const float*)d_in[10];
    const float* num_b   = (const float*)d_in[11];
    const float* cat_w   = (const float*)d_in[12];
    const float* cat_b   = (const float*)d_in[13];
    const float* rel_w   = (const float*)d_in[14];
    const float* root_w  = (const float*)d_in[15];
    const float* rgcn_b  = (const float*)d_in[16];
    const float* mlp_w1  = (const float*)d_in[17];
    const float* mlp_b1  = (const float*)d_in[18];
    const float* mlp_w2  = (const float*)d_in[19];
    const float* mlp_b2  = (const float*)d_in[20];
    float* out = (float*)d_out;

    __half *px, *ph, *py, *proot;
    uint32_t *pbt;
    int *pcnt, *ptotal;
    cudaGetSymbolAddress((void**)&px,     g_x);
    cudaGetSymbolAddress((void**)&ph,     g_h);
    cudaGetSymbolAddress((void**)&py,     g_y);
    cudaGetSymbolAddress((void**)&proot,  g_root);
    cudaGetSymbolAddress((void**)&pbt,    g_bt);
    cudaGetSymbolAddress((void**)&pcnt,   g_cnt);
    cudaGetSymbolAddress((void**)&ptotal, g_total);

    cudaFuncSetAttribute(k_rgcn3, cudaFuncAttributeMaxDynamicSharedMemorySize, RGCN_SMEM);

    // L0: zero counters (async memset — graph-capturable, no allocation)
    cudaMemsetAsync(pcnt, 0, 2 * NN * sizeof(int));
    cudaMemsetAsync(ptotal, 0, sizeof(int));

    // L1: prep all weights ∥ hist
    k_L1<<<640 + 6250, 256>>>(des_w, tweet_w, rel_w, root_w, mlp_w1, pbt, ei, et);

    // L2: des-GEMM ∥ tweets-GEMM ∥ assign (hist complete)
    k_L2<<<782 + 196, 256>>>(des, tweets, pbt, des_b, tweet_b, px, ph);

    // L3: combine ∥ fill (assign complete)
    k_L3<<<6250 + 6250, 256>>>(numf, catf, num_w, num_b, cat_w, cat_b,
                               px, ph, px, ei, et);

    // L4: RGCN layer 0 (pure GEMM)
    k_rgcn3<<<391, 256, RGCN_SMEM>>>(px, pbt + BT_REL, pbt + BT_REL + 8192,
                                     pbt + BT_ROOT, py, proot);
    k_gather<<<(NN * 32) / 256, 256>>>(py, proot, rgcn_b, px);

    // L6: RGCN layer 1
    k_rgcn3<<<391, 256, RGCN_SMEM>>>(px, pbt + BT_REL + 2 * 8192, pbt + BT_REL + 3 * 8192,
                                     pbt + BT_ROOT + 8192, py, proot);
    k_gather<<<(NN * 32) / 256, 256>>>(py, proot, rgcn_b + 128, px);

    // L8: MLP1 + fused head
    k_mlp_head<<<391, 256>>>(px, pbt + BT_MLP1, mlp_b1, mlp_w2, mlp_b2, out);
}

// round 15
// speedup vs baseline: 1.0950x; 1.0029x over previous
#include <cuda_runtime.h>
#include <cuda_bf16.h>
#include <cuda_fp16.h>
#include <cstdint>

#define NN 50000
#define EE 1600000

// ---------------- scratch (device globals) ----------------------------------
__device__ __half g_x[NN * 128];     // node features fp16 (px)
__device__ __half g_h[NN * 128];     // tweets projection fp16
__device__ __half g_y[NN * 256];     // [Y0 | Y1] per node, fp16 messages
__device__ __half g_root[NN * 128];  // root projection fp16
__device__ uint32_t g_bt[155648];    // pre-packed fp16 weights (frag order)
__device__ int   g_cnt[2 * NN];
__device__ int   g_off[NN];
__device__ int   g_len[NN];
__device__ int   g_cur[NN];
__device__ int   g_list[EE];
__device__ float g_inv[2 * NN];
__device__ int   g_total;

// BT offsets in uint32 words (each word = half2)
#define BT_DES  0
#define BT_TWE  49152
#define BT_REL  98304         // + i*8192
#define BT_ROOT 131072        // + l*8192
#define BT_MLP1 147456

__device__ __forceinline__ float lrelu(float v) { return v > 0.f ? v : 0.01f * v; }

__device__ __forceinline__ uint32_t smem_u32(const void* p) {
    uint32_t a;
    asm("{ .reg .u64 t; cvta.to.shared.u64 t, %1; cvt.u32.u64 %0, t; }" : "=r"(a) : "l"(p));
    return a;
}

__device__ __forceinline__ void mma_f16(float c[4], const uint32_t a[4], const uint32_t b[2]) {
    asm volatile("mma.sync.aligned.m16n8k16.row.col.f32.f16.f16.f32 "
        "{%0,%1,%2,%3}, {%4,%5,%6,%7}, {%8,%9}, {%0,%1,%2,%3};"
        : "+f"(c[0]), "+f"(c[1]), "+f"(c[2]), "+f"(c[3])
        : "r"(a[0]), "r"(a[1]), "r"(a[2]), "r"(a[3]), "r"(b[0]), "r"(b[1]));
}

__device__ __forceinline__ void ldsm_x4(uint32_t r[4], uint32_t addr) {
    asm volatile("ldmatrix.sync.aligned.m8n8.x4.shared.b16 {%0,%1,%2,%3}, [%4];"
        : "=r"(r[0]), "=r"(r[1]), "=r"(r[2]), "=r"(r[3]) : "r"(addr));
}

__device__ __forceinline__ uint32_t h2u(__half2 h) { return *(uint32_t*)&h; }

// ---------------- device helpers ---------------------------------------------
__device__ __forceinline__ void dev_prep_b16(const float* __restrict__ src,
                                             uint32_t* __restrict__ dst, int K, int blk) {
    int w = blk * 256 + threadIdx.x;
    if (w >= K * 64) return;
    int kt = w >> 10;
    int within = w & 1023;
    int n8 = within >> 6;
    int rem = within & 63;
    int lane = rem >> 1;
    int j = rem & 1;
    int n = n8 * 8 + (lane >> 2);
    int k0 = kt * 16 + j * 8 + 2 * (lane & 3);
    __half2 h = __floats2half2_rn(src[(size_t)k0 * 128 + n], src[(size_t)(k0 + 1) * 128 + n]);
    dst[w] = h2u(h);
}

__device__ __forceinline__ void dev_hist(const int* __restrict__ ei,
                                         const int* __restrict__ et, int blk) {
    int e = blk * 256 + threadIdx.x;
    if (e < EE) atomicAdd(&g_cnt[et[e] * NN + ei[EE + e]], 1);
}

__device__ __forceinline__ void dev_fill(const int* __restrict__ ei,
                                         const int* __restrict__ et, int blk) {
    int e = blk * 256 + threadIdx.x;
    if (e < EE) {
        int pos = atomicAdd(&g_cur[ei[EE + e]], 1);
        g_list[pos] = (ei[e] << 1) | et[e];
    }
}

// A smem layout per ktile (1024 words): row r occupies words r*8..r*8+7;
// 16B chunk cc stored at position (cc ^ ((r>>2)&1)).
__device__ __forceinline__ uint32_t a_off16(int r, int c4) {
    return (uint32_t)(r * 8 + (((c4 >> 1) ^ ((r >> 2) & 1)) << 2) + (c4 & 1) * 2);
}

__device__ __forceinline__ uint32_t ldsm_row_off(int lane) {
    int r_local = (lane & 7) | (((lane >> 3) & 1) << 3);
    return (uint32_t)(r_local * 8 + ((((lane >> 4) & 1) ^ ((r_local >> 2) & 1)) << 2));
}

// ---------------- fp16 GEMM body ----------------------------------------------
template <int ACT, bool AHALF, bool OUTHALF>
__device__ __forceinline__ void gemm_body16(
    const void* __restrict__ Av, const uint32_t* __restrict__ Bp,
    const float* __restrict__ bias, void* __restrict__ Cv,
    int M, int K, int ldc, int bidx,
    uint32_t (*As)[1024]) {

    int tid  = threadIdx.x;
    int lane = tid & 31;
    int w    = tid >> 5;
    int wm   = w & 1;
    int wn   = w >> 1;
    int m0   = bidx * 128;
    int grp  = lane >> 2;
    int q    = lane & 3;

    float acc[4][4][4];
    #pragma unroll
    for (int i = 0; i < 4; i++)
        #pragma unroll
        for (int j = 0; j < 4; j++)
            #pragma unroll
            for (int v = 0; v < 4; v++) acc[i][j][v] = 0.f;

    uint4 ra4[2];
    uint2 ra2[2];

    auto ldg_tile = [&](int kc) {
        #pragma unroll
        for (int u = 0; u < 2; u++) {
            int unit = tid + u * 256;
            int row  = unit >> 2;
            int c4   = unit & 3;
            int ar   = m0 + row; if (ar >= M) ar = M - 1;
            if (AHALF) {
                const __half* Ah = (const __half*)Av;
                ra2[u] = *(const uint2*)&Ah[(size_t)ar * K + kc + c4 * 4];
            } else {
                const float* Af = (const float*)Av;
                ra4[u] = *(const uint4*)&Af[(size_t)ar * K + kc + c4 * 4];
            }
        }
    };

    auto sts_tile = [&](int st) {
        #pragma unroll
        for (int u = 0; u < 2; u++) {
            int unit = tid + u * 256;
            uint32_t off = a_off16(unit >> 2, unit & 3);
            if (AHALF) {
                *(uint2*)&As[st][off] = ra2[u];
            } else {
                const float* vf = (const float*)&ra4[u];
                __half2 h0 = __floats2half2_rn(vf[0], vf[1]);
                __half2 h1 = __floats2half2_rn(vf[2], vf[3]);
                *(uint2*)&As[st][off] = make_uint2(h2u(h0), h2u(h1));
            }
        }
    };

    uint32_t sbase = smem_u32(&As[0][0]);
    uint32_t lro4  = ldsm_row_off(lane) * 4;

    auto compute = [&](int kt, int st) {
        const uint32_t* bbase = Bp + (size_t)kt * 1024;
        uint2 bf[4];
        #pragma unroll
        for (int nf = 0; nf < 4; nf++)
            bf[nf] = *(const uint2*)&bbase[(wn * 4 + nf) * 64 + lane * 2];
        uint32_t af[4][4];
        #pragma unroll
        for (int mf = 0; mf < 4; mf++)
            ldsm_x4(af[mf], sbase + (uint32_t)(st * 1024 + (wm * 4 + mf) * 128) * 4 + lro4);
        #pragma unroll
        for (int mf = 0; mf < 4; mf++)
            #pragma unroll
            for (int nf = 0; nf < 4; nf++)
                mma_f16(acc[mf][nf], af[mf], (const uint32_t*)&bf[nf]);
    };

    int nk = K >> 4;
    ldg_tile(0);
    sts_tile(0);
    if (nk > 1) ldg_tile(16);
    __syncthreads();

    for (int kt = 0; kt < nk; kt++) {
        int st = kt & 1;
        compute(kt, st);
        if (kt + 1 < nk) {
            sts_tile(st ^ 1);
            if (kt + 2 < nk) ldg_tile((kt + 2) * 16);
        }
        __syncthreads();
    }

    #pragma unroll
    for (int mf = 0; mf < 4; mf++) {
        int rbase = m0 + wm * 64 + mf * 16 + grp;
        #pragma unroll
        for (int half = 0; half < 2; half++) {
            int row = rbase + half * 8;
            if (row >= M) continue;
            #pragma unroll
            for (int nf = 0; nf < 4; nf++) {
                int col = wn * 32 + nf * 8 + q * 2;
                float v0 = acc[mf][nf][half * 2 + 0];
                float v1 = acc[mf][nf][half * 2 + 1];
                if (bias) { v0 += bias[col]; v1 += bias[col + 1]; }
                if (ACT == 1) { v0 = lrelu(v0); v1 = lrelu(v1); }
                else if (ACT == 2) { v0 = fmaxf(v0, 0.f); v1 = fmaxf(v1, 0.f); }
                if (OUTHALF) {
                    __half* Ch = (__half*)Cv;
                    *(__half2*)&Ch[(size_t)row * ldc + col] = __floats2half2_rn(v0, v1);
                } else {
                    float* Cf = (float*)Cv;
                    Cf[(size_t)row * ldc + col]     = v0;
                    Cf[(size_t)row * ldc + col + 1] = v1;
                }
            }
        }
    }
}

// ---------------- L1: prep all weights (counters zeroed by memset) -----------
__global__ void k_L1(const float* __restrict__ des_w, const float* __restrict__ tweet_w,
                     const float* __restrict__ rel_w, const float* __restrict__ root_w,
                     const float* __restrict__ mlp_w1, uint32_t* __restrict__ bt) {
    int pb = blockIdx.x;
    if (pb < 192)       dev_prep_b16(des_w,   bt + BT_DES, 768, pb);
    else if (pb < 384)  dev_prep_b16(tweet_w, bt + BT_TWE, 768, pb - 192);
    else if (pb < 512)  { int i = (pb - 384) >> 5;
                          dev_prep_b16(rel_w + (size_t)i * 16384, bt + BT_REL + i * 8192, 128, (pb - 384) & 31); }
    else if (pb < 576)  { int l = (pb - 512) >> 5;
                          dev_prep_b16(root_w + (size_t)l * 16384, bt + BT_ROOT + l * 8192, 128, (pb - 512) & 31); }
    else                dev_prep_b16(mlp_w1, bt + BT_MLP1, 128, pb - 576);
}

// ---------------- L2: des-GEMM ∥ tweets-GEMM ∥ hist ---------------------------
__global__ void __launch_bounds__(256, 2)
k_L2(const float* __restrict__ des, const float* __restrict__ tweets,
     const uint32_t* __restrict__ bt, const float* __restrict__ des_b,
     const float* __restrict__ tweet_b, __half* __restrict__ ox,
     __half* __restrict__ oh, const int* __restrict__ ei, const int* __restrict__ et) {
    __shared__ uint32_t As[2][1024];
    int bid = blockIdx.x;
    if (bid < 391)
        gemm_body16<1, false, true>(des, bt + BT_DES, des_b, ox, NN, 768, 128, bid, As);
    else if (bid < 782)
        gemm_body16<1, false, true>(tweets, bt + BT_TWE, tweet_b, oh, NN, 768, 128, bid - 391, As);
    else
        dev_hist(ei, et, bid - 782);
}

// ---------------- assign (needs hist complete) --------------------------------
__global__ void k_assign() {
    int i = blockIdx.x * 256 + threadIdx.x;
    if (i >= NN) return;
    int c0 = g_cnt[i], c1 = g_cnt[NN + i];
    int deg = c0 + c1;
    int pos = atomicAdd(&g_total, deg);
    g_off[i] = pos;
    g_cur[i] = pos;
    g_len[i] = deg;
    g_inv[i]      = 1.0f / (c0 > 0 ? (float)c0 : 1.0f);
    g_inv[NN + i] = 1.0f / (c1 > 0 ? (float)c1 : 1.0f);
}

// ---------------- L3: combine (fp16 in/out) ∥ fill -----------------------------
__global__ void k_L3(const float* __restrict__ numf, const float* __restrict__ catf,
                     const float* __restrict__ num_w, const float* __restrict__ num_b,
                     const float* __restrict__ cat_w, const float* __restrict__ cat_b,
                     const __half* __restrict__ gx, const __half* __restrict__ gh,
                     __half* __restrict__ px,
                     const int* __restrict__ ei, const int* __restrict__ et) {
    int bid = blockIdx.x;
    if (bid >= 6250) { dev_fill(ei, et, bid - 6250); return; }
    int wid  = threadIdx.x >> 5;
    int lane = threadIdx.x & 31;
    int row  = bid * 8 + wid;
    if (row >= NN) return;

    float nv[5], cv[6];
    #pragma unroll
    for (int k = 0; k < 5; k++) nv[k] = numf[row * 5 + k];
    #pragma unroll
    for (int k = 0; k < 6; k++) cv[k] = catf[row * 6 + k];

    size_t base = (size_t)row * 128 + lane * 4;
    uint2 au = *(const uint2*)&gx[base];
    uint2 bu = *(const uint2*)&gh[base];
    float2 a01 = __half22float2(*(const __half2*)&au.x);
    float2 a23 = __half22float2(*(const __half2*)&au.y);
    float2 b01 = __half22float2(*(const __half2*)&bu.x);
    float2 b23 = __half22float2(*(const __half2*)&bu.y);
    float af[4] = {a01.x, a01.y, a23.x, a23.y};
    float bf[4] = {b01.x, b01.y, b23.x, b23.y};

    float o[4];
    #pragma unroll
    for (int u = 0; u < 4; u++) {
        int col = lane * 4 + u;
        float s = num_b[col];
        #pragma unroll
        for (int k = 0; k < 5; k++) s = fmaf(nv[k], num_w[k * 128 + col], s);
        float t = cat_b[col];
        #pragma unroll
        for (int k = 0; k < 6; k++) t = fmaf(cv[k], cat_w[k * 128 + col], t);
        o[u] = af[u] + bf[u] + lrelu(s) + lrelu(t);
    }
    __half2 h0 = __floats2half2_rn(o[0], o[1]);
    __half2 h1 = __floats2half2_rn(o[2], o[3]);
    *(uint2*)&px[base] = make_uint2(h2u(h0), h2u(h1));
}

// ---------------- RGCN multi-B GEMM: fp16 A resident, fp16 outputs -----------
__global__ void __launch_bounds__(256, 2)
k_rgcn3(const __half* __restrict__ px,
        const uint32_t* __restrict__ b0p, const uint32_t* __restrict__ b1p,
        const uint32_t* __restrict__ b2p,
        __half* __restrict__ py, __half* __restrict__ proot) {
    extern __shared__ uint32_t Asm[];
    int bid = blockIdx.x;

    int tid  = threadIdx.x;
    int lane = tid & 31;
    int w    = tid >> 5;
    int wm   = w & 1;
    int wn   = w >> 1;
    int m0   = bid * 128;
    int grp  = lane >> 2;
    int q    = lane & 3;

    #pragma unroll
    for (int kt = 0; kt < 8; kt++) {
        #pragma unroll
        for (int u = 0; u < 2; u++) {
            int unit = tid + u * 256;
            int row  = unit >> 2;
            int c4   = unit & 3;
            int ar   = m0 + row; if (ar >= NN) ar = NN - 1;
            uint2 ra = *(const uint2*)&px[(size_t)ar * 128 + kt * 16 + c4 * 4];
            *(uint2*)&Asm[kt * 1024 + a_off16(row, c4)] = ra;
        }
    }
    __syncthreads();

    const uint32_t* bsel[3] = { b0p, b1p, b2p };
    uint32_t sbase = smem_u32(Asm);
    uint32_t lro4  = ldsm_row_off(lane) * 4;

    #pragma unroll
    for (int b = 0; b < 3; b++) {
        const uint32_t* Bp = bsel[b];

        float acc[4][4][4];
        #pragma unroll
        for (int i = 0; i < 4; i++)
            #pragma unroll
            for (int j = 0; j < 4; j++)
                #pragma unroll
                for (int v = 0; v < 4; v++) acc[i][j][v] = 0.f;

        #pragma unroll
        for (int kt = 0; kt < 8; kt++) {
            const uint32_t* bbase = Bp + (size_t)kt * 1024;
            uint2 bf[4];
            #pragma unroll
            for (int nf = 0; nf < 4; nf++)
                bf[nf] = *(const uint2*)&bbase[(wn * 4 + nf) * 64 + lane * 2];
            uint32_t af[4][4];
            #pragma unroll
            for (int mf = 0; mf < 4; mf++)
                ldsm_x4(af[mf], sbase + (uint32_t)(kt * 1024 + (wm * 4 + mf) * 128) * 4 + lro4);
            #pragma unroll
            for (int mf = 0; mf < 4; mf++)
                #pragma unroll
                for (int nf = 0; nf < 4; nf++)
                    mma_f16(acc[mf][nf], af[mf], (const uint32_t*)&bf[nf]);
        }

        #pragma unroll
        for (int mf = 0; mf < 4; mf++) {
            int rbase = m0 + wm * 64 + mf * 16 + grp;
            #pragma unroll
            for (int half = 0; half < 2; half++) {
                int row = rbase + half * 8;
                if (row >= NN) continue;
                #pragma unroll
                for (int nf = 0; nf < 4; nf++) {
                    int col = wn * 32 + nf * 8 + q * 2;
                    __half2 hv = __floats2half2_rn(acc[mf][nf][half * 2 + 0],
                                                   acc[mf][nf][half * 2 + 1]);
                    if (b == 2)
                        *(__half2*)&proot[(size_t)row * 128 + col] = hv;
                    else
                        *(__half2*)&py[(size_t)row * 256 + b * 128 + col] = hv;
                }
            }
        }
    }
}

// ---------------- gather (fp16 in, fp32 accumulate, fp16 out) ----------------
__global__ void k_gather(const __half* __restrict__ y, const __half* __restrict__ root,
                         const float* __restrict__ bias, __half* __restrict__ xout) {
    int gw = (blockIdx.x * blockDim.x + threadIdx.x) >> 5;
    int lane = threadIdx.x & 31;
    if (gw >= NN) return;

    int beg = g_off[gw], len = g_len[gw];
    float a0[4] = {0.f, 0.f, 0.f, 0.f};
    float a1[4] = {0.f, 0.f, 0.f, 0.f};

    for (int j = 0; j < len; j++) {
        int p = __ldg(&g_list[beg + j]);
        const uint2 raw = *(const uint2*)(y + (size_t)(p >> 1) * 256 + (p & 1) * 128 + lane * 4);
        float2 f01 = __half22float2(*(const __half2*)&raw.x);
        float2 f23 = __half22float2(*(const __half2*)&raw.y);
        if (p & 1) { a1[0] += f01.x; a1[1] += f01.y; a1[2] += f23.x; a1[3] += f23.y; }
        else       { a0[0] += f01.x; a0[1] += f01.y; a0[2] += f23.x; a0[3] += f23.y; }
    }

    float i0 = g_inv[gw], i1 = g_inv[NN + gw];
    size_t base = (size_t)gw * 128 + lane * 4;
    uint2 ru = *(const uint2*)&root[base];
    float2 r01 = __half22float2(*(const __half2*)&ru.x);
    float2 r23 = __half22float2(*(const __half2*)&ru.y);
    float b0 = bias[lane * 4 + 0], b1 = bias[lane * 4 + 1];
    float b2 = bias[lane * 4 + 2], b3 = bias[lane * 4 + 3];

    float o0 = lrelu(r01.x + b0 + a0[0] * i0 + a1[0] * i1);
    float o1 = lrelu(r01.y + b1 + a0[1] * i0 + a1[1] * i1);
    float o2 = lrelu(r23.x + b2 + a0[2] * i0 + a1[2] * i1);
    float o3 = lrelu(r23.y + b3 + a0[3] * i0 + a1[3] * i1);
    __half2 h0 = __floats2half2_rn(o0, o1);
    __half2 h1 = __floats2half2_rn(o2, o3);
    *(uint2*)&xout[base] = make_uint2(h2u(h0), h2u(h1));
}

// ---------------- L8: MLP1 fp16 GEMM + fused 2-wide head ----------------------
__global__ void __launch_bounds__(256, 2)
k_mlp_head(const __half* __restrict__ A, const uint32_t* __restrict__ Bp,
           const float* __restrict__ b1, const float* __restrict__ w2,
           const float* __restrict__ b2, float* __restrict__ out) {
    __shared__ uint32_t As[2][1024];
    __shared__ float w2s[256];
    __shared__ float outs[128][2];

    int tid  = threadIdx.x;
    int lane = tid & 31;
    int w    = tid >> 5;
    int wm   = w & 1;
    int wn   = w >> 1;
    int m0   = blockIdx.x * 128;
    int grp  = lane >> 2;
    int q    = lane & 3;

    w2s[tid & 255] = w2[tid & 255];
    outs[tid >> 1][tid & 1] = 0.f;

    float acc[4][4][4];
    #pragma unroll
    for (int i = 0; i < 4; i++)
        #pragma unroll
        for (int j = 0; j < 4; j++)
            #pragma unroll
            for (int v = 0; v < 4; v++) acc[i][j][v] = 0.f;

    uint2 ra[2];
    const int K = 128;

    auto ldg_tile = [&](int kc) {
        #pragma unroll
        for (int u = 0; u < 2; u++) {
            int unit = tid + u * 256;
            int row  = unit >> 2;
            int c4   = unit & 3;
            int ar   = m0 + row; if (ar >= NN) ar = NN - 1;
            ra[u] = *(const uint2*)&A[(size_t)ar * K + kc + c4 * 4];
        }
    };
    auto sts_tile = [&](int st) {
        #pragma unroll
        for (int u = 0; u < 2; u++) {
            int unit = tid + u * 256;
            *(uint2*)&As[st][a_off16(unit >> 2, unit & 3)] = ra[u];
        }
    };
    uint32_t sbase = smem_u32(&As[0][0]);
    uint32_t lro4  = ldsm_row_off(lane) * 4;
    auto compute = [&](int kt, int st) {
        const uint32_t* bbase = Bp + (size_t)kt * 1024;
        uint2 bf[4];
        #pragma unroll
        for (int nf = 0; nf < 4; nf++)
            bf[nf] = *(const uint2*)&bbase[(wn * 4 + nf) * 64 + lane * 2];
        uint32_t af[4][4];
        #pragma unroll
        for (int mf = 0; mf < 4; mf++)
            ldsm_x4(af[mf], sbase + (uint32_t)(st * 1024 + (wm * 4 + mf) * 128) * 4 + lro4);
        #pragma unroll
        for (int mf = 0; mf < 4; mf++)
            #pragma unroll
            for (int nf = 0; nf < 4; nf++)
                mma_f16(acc[mf][nf], af[mf], (const uint32_t*)&bf[nf]);
    };

    int nk = K >> 4;   // 8
    ldg_tile(0);
    sts_tile(0);
    ldg_tile(16);
    __syncthreads();
    for (int kt = 0; kt < nk; kt++) {
        int st = kt & 1;
        compute(kt, st);
        if (kt + 1 < nk) {
            sts_tile(st ^ 1);
            if (kt + 2 < nk) ldg_tile((kt + 2) * 16);
        }
        __syncthreads();
    }

    // head: out[row] = relu(acc + b1) @ w2 + b2
    #pragma unroll
    for (int mf = 0; mf < 4; mf++) {
        #pragma unroll
        for (int half = 0; half < 2; half++) {
            int rl = wm * 64 + mf * 16 + grp + half * 8;
            float p0 = 0.f, p1 = 0.f;
            #pragma unroll
            for (int nf = 0; nf < 4; nf++) {
                #pragma unroll
                for (int v = 0; v < 2; v++) {
                    int col = wn * 32 + nf * 8 + q * 2 + v;
                    float h = fmaxf(acc[mf][nf][half * 2 + v] + b1[col], 0.f);
                    p0 = fmaf(h, w2s[col * 2 + 0], p0);
                    p1 = fmaf(h, w2s[col * 2 + 1], p1);
                }
            }
            p0 += __shfl_xor_sync(0xFFFFFFFFu, p0, 1);
            p0 += __shfl_xor_sync(0xFFFFFFFFu, p0, 2);
            p1 += __shfl_xor_sync(0xFFFFFFFFu, p1, 1);
            p1 += __shfl_xor_sync(0xFFFFFFFFu, p1, 2);
            if (q == 0) {
                atomicAdd(&outs[rl][0], p0);
                atomicAdd(&outs[rl][1], p1);
            }
        }
    }
    __syncthreads();
    int r = tid >> 1, c = tid & 1;
    int row = m0 + r;
    if (row < NN) out[row * 2 + c] = outs[r][c] + b2[c];
}

// ---------------- launch -------------------------------------------------------
#define RGCN_SMEM 32768

extern "C" void kernel_launch(void* const* d_in, const int* in_sizes, int n_in,
                              void* d_out, int out_size) {
    const float* des     = (const float*)d_in[0];
    const float* tweets  = (const float*)d_in[1];
    const float* numf    = (const float*)d_in[2];
    const float* catf    = (const float*)d_in[3];
    const int*   ei      = (const int*)d_in[4];
    const int*   et      = (const int*)d_in[5];
    const float* des_w   = (const float*)d_in[6];
    const float* des_b   = (const float*)d_in[7];
    const float* tweet_w = (const float*)d_in[8];
    const float* tweet_b = (const float*)d_in[9];
    const float* num_w   = (const float*)d_in[10];
    const float* num_b   = (const float*)d_in[11];
    const float* cat_w   = (const float*)d_in[12];
    const float* cat_b   = (const float*)d_in[13];
    const float* rel_w   = (const float*)d_in[14];
    const float* root_w  = (const float*)d_in[15];
    const float* rgcn_b  = (const float*)d_in[16];
    const float* mlp_w1  = (const float*)d_in[17];
    const float* mlp_b1  = (const float*)d_in[18];
    const float* mlp_w2  = (const float*)d_in[19];
    const float* mlp_b2  = (const float*)d_in[20];
    float* out = (float*)d_out;

    __half *px, *ph, *py, *proot;
    uint32_t *pbt;
    int *pcnt, *ptotal;
    cudaGetSymbolAddress((void**)&px,     g_x);
    cudaGetSymbolAddress((void**)&ph,     g_h);
    cudaGetSymbolAddress((void**)&py,     g_y);
    cudaGetSymbolAddress((void**)&proot,  g_root);
    cudaGetSymbolAddress((void**)&pbt,    g_bt);
    cudaGetSymbolAddress((void**)&pcnt,   g_cnt);
    cudaGetSymbolAddress((void**)&ptotal, g_total);

    cudaFuncSetAttribute(k_rgcn3, cudaFuncAttributeMaxDynamicSharedMemorySize, RGCN_SMEM);

    // L0: zero counters (async memset — graph-capturable)
    cudaMemsetAsync(pcnt, 0, 2 * NN * sizeof(int));
    cudaMemsetAsync(ptotal, 0, sizeof(int));

    // L1: prep all weights (fast, small)
    k_L1<<<608, 256>>>(des_w, tweet_w, rel_w, root_w, mlp_w1, pbt);

    // L2: des-GEMM ∥ tweets-GEMM ∥ hist (hist hides under big GEMMs)
    k_L2<<<782 + 6250, 256>>>(des, tweets, pbt, des_b, tweet_b, px, ph, ei, et);

    // assign (hist complete)
    k_assign<<<196, 256>>>();

    // L3: combine ∥ fill
    k_L3<<<6250 + 6250, 256>>>(numf, catf, num_w, num_b, cat_w, cat_b,
                               px, ph, px, ei, et);

    // L4: RGCN layer 0 (pure GEMM)
    k_rgcn3<<<391, 256, RGCN_SMEM>>>(px, pbt + BT_REL, pbt + BT_REL + 8192,
                                     pbt + BT_ROOT, py, proot);
    k_gather<<<(NN * 32) / 256, 256>>>(py, proot, rgcn_b, px);

    // L6: RGCN layer 1
    k_rgcn3<<<391, 256, RGCN_SMEM>>>(px, pbt + BT_REL + 2 * 8192, pbt + BT_REL + 3 * 8192,
                                     pbt + BT_ROOT + 8192, py, proot);
    k_gather<<<(NN * 32) / 256, 256>>>(py, proot, rgcn_b + 128, px);

    // L8: MLP1 + fused head
    k_mlp_head<<<391, 256>>>(px, pbt + BT_MLP1, mlp_b1, mlp_w2, mlp_b2, out);
}

// round 16
// speedup vs baseline: 1.1395x; 1.0406x over previous
#include <cuda_runtime.h>
#include <cuda_bf16.h>
#include <cuda_fp16.h>
#include <cstdint>

#define NN 50000
#define EE 1600000

// ---------------- scratch (device globals) ----------------------------------
__device__ __half g_x[NN * 128];     // node features fp16 (px)
__device__ __half g_h[NN * 128];     // tweets projection fp16
__device__ __half g_y[NN * 256];     // [Y0 | Y1] per node, fp16 messages
__device__ __half g_root[NN * 128];  // root projection fp16
__device__ uint32_t g_bt[155648];    // pre-packed fp16 weights (frag order)
__device__ int   g_cnt[2 * NN];
__device__ int   g_off[NN];
__device__ int   g_len[NN];
__device__ int   g_cur[NN];
__device__ int   g_list[EE];
__device__ float g_inv[2 * NN];
__device__ int   g_total;

// BT offsets in uint32 words (each word = half2)
#define BT_DES  0
#define BT_TWE  49152
#define BT_REL  98304         // + i*8192
#define BT_ROOT 131072        // + l*8192
#define BT_MLP1 147456

__device__ __forceinline__ float lrelu(float v) { return v > 0.f ? v : 0.01f * v; }

__device__ __forceinline__ uint32_t smem_u32(const void* p) {
    uint32_t a;
    asm("{ .reg .u64 t; cvta.to.shared.u64 t, %1; cvt.u32.u64 %0, t; }" : "=r"(a) : "l"(p));
    return a;
}

__device__ __forceinline__ void mma_f16(float c[4], const uint32_t a[4], const uint32_t b[2]) {
    asm volatile("mma.sync.aligned.m16n8k16.row.col.f32.f16.f16.f32 "
        "{%0,%1,%2,%3}, {%4,%5,%6,%7}, {%8,%9}, {%0,%1,%2,%3};"
        : "+f"(c[0]), "+f"(c[1]), "+f"(c[2]), "+f"(c[3])
        : "r"(a[0]), "r"(a[1]), "r"(a[2]), "r"(a[3]), "r"(b[0]), "r"(b[1]));
}

__device__ __forceinline__ void ldsm_x4(uint32_t r[4], uint32_t addr) {
    asm volatile("ldmatrix.sync.aligned.m8n8.x4.shared.b16 {%0,%1,%2,%3}, [%4];"
        : "=r"(r[0]), "=r"(r[1]), "=r"(r[2]), "=r"(r[3]) : "r"(addr));
}

__device__ __forceinline__ uint32_t h2u(__half2 h) { return *(uint32_t*)&h; }

// ---------------- device helpers ---------------------------------------------
__device__ __forceinline__ void dev_prep_b16(const float* __restrict__ src,
                                             uint32_t* __restrict__ dst, int K, int blk) {
    int w = blk * 256 + threadIdx.x;
    if (w >= K * 64) return;
    int kt = w >> 10;
    int within = w & 1023;
    int n8 = within >> 6;
    int rem = within & 63;
    int lane = rem >> 1;
    int j = rem & 1;
    int n = n8 * 8 + (lane >> 2);
    int k0 = kt * 16 + j * 8 + 2 * (lane & 3);
    __half2 h = __floats2half2_rn(src[(size_t)k0 * 128 + n], src[(size_t)(k0 + 1) * 128 + n]);
    dst[w] = h2u(h);
}

__device__ __forceinline__ void dev_hist(const int* __restrict__ ei,
                                         const int* __restrict__ et, int blk) {
    int e = blk * 256 + threadIdx.x;
    if (e < EE) atomicAdd(&g_cnt[et[e] * NN + ei[EE + e]], 1);
}

__device__ __forceinline__ void dev_assign(int blk) {
    int i = blk * 256 + threadIdx.x;
    if (i >= NN) return;
    int c0 = g_cnt[i], c1 = g_cnt[NN + i];
    int deg = c0 + c1;
    int pos = atomicAdd(&g_total, deg);
    g_off[i] = pos;
    g_cur[i] = pos;
    g_len[i] = deg;
    g_inv[i]      = 1.0f / (c0 > 0 ? (float)c0 : 1.0f);
    g_inv[NN + i] = 1.0f / (c1 > 0 ? (float)c1 : 1.0f);
}

__device__ __forceinline__ void dev_fill(const int* __restrict__ ei,
                                         const int* __restrict__ et, int blk) {
    int e = blk * 256 + threadIdx.x;
    if (e < EE) {
        int pos = atomicAdd(&g_cur[ei[EE + e]], 1);
        g_list[pos] = (ei[e] << 1) | et[e];
    }
}

// A smem layout per ktile (1024 words): row r occupies words r*8..r*8+7;
// 16B chunk cc stored at position (cc ^ ((r>>2)&1)).
__device__ __forceinline__ uint32_t a_off16(int r, int c4) {
    return (uint32_t)(r * 8 + (((c4 >> 1) ^ ((r >> 2) & 1)) << 2) + (c4 & 1) * 2);
}

__device__ __forceinline__ uint32_t ldsm_row_off(int lane) {
    int r_local = (lane & 7) | (((lane >> 3) & 1) << 3);
    return (uint32_t)(r_local * 8 + ((((lane >> 4) & 1) ^ ((r_local >> 2) & 1)) << 2));
}

// ---------------- fp16 GEMM body ----------------------------------------------
template <int ACT, bool AHALF, bool OUTHALF>
__device__ __forceinline__ void gemm_body16(
    const void* __restrict__ Av, const uint32_t* __restrict__ Bp,
    const float* __restrict__ bias, void* __restrict__ Cv,
    int M, int K, int ldc, int bidx,
    uint32_t (*As)[1024]) {

    int tid  = threadIdx.x;
    int lane = tid & 31;
    int w    = tid >> 5;
    int wm   = w & 1;
    int wn   = w >> 1;
    int m0   = bidx * 128;
    int grp  = lane >> 2;
    int q    = lane & 3;

    float acc[4][4][4];
    #pragma unroll
    for (int i = 0; i < 4; i++)
        #pragma unroll
        for (int j = 0; j < 4; j++)
            #pragma unroll
            for (int v = 0; v < 4; v++) acc[i][j][v] = 0.f;

    uint4 ra4[2];
    uint2 ra2[2];

    auto ldg_tile = [&](int kc) {
        #pragma unroll
        for (int u = 0; u < 2; u++) {
            int unit = tid + u * 256;
            int row  = unit >> 2;
            int c4   = unit & 3;
            int ar   = m0 + row; if (ar >= M) ar = M - 1;
            if (AHALF) {
                const __half* Ah = (const __half*)Av;
                ra2[u] = *(const uint2*)&Ah[(size_t)ar * K + kc + c4 * 4];
            } else {
                const float* Af = (const float*)Av;
                ra4[u] = *(const uint4*)&Af[(size_t)ar * K + kc + c4 * 4];
            }
        }
    };

    auto sts_tile = [&](int st) {
        #pragma unroll
        for (int u = 0; u < 2; u++) {
            int unit = tid + u * 256;
            uint32_t off = a_off16(unit >> 2, unit & 3);
            if (AHALF) {
                *(uint2*)&As[st][off] = ra2[u];
            } else {
                const float* vf = (const float*)&ra4[u];
                __half2 h0 = __floats2half2_rn(vf[0], vf[1]);
                __half2 h1 = __floats2half2_rn(vf[2], vf[3]);
                *(uint2*)&As[st][off] = make_uint2(h2u(h0), h2u(h1));
            }
        }
    };

    uint32_t sbase = smem_u32(&As[0][0]);
    uint32_t lro4  = ldsm_row_off(lane) * 4;

    auto compute = [&](int kt, int st) {
        const uint32_t* bbase = Bp + (size_t)kt * 1024;
        uint2 bf[4];
        #pragma unroll
        for (int nf = 0; nf < 4; nf++)
            bf[nf] = *(const uint2*)&bbase[(wn * 4 + nf) * 64 + lane * 2];
        uint32_t af[4][4];
        #pragma unroll
        for (int mf = 0; mf < 4; mf++)
            ldsm_x4(af[mf], sbase + (uint32_t)(st * 1024 + (wm * 4 + mf) * 128) * 4 + lro4);
        #pragma unroll
        for (int mf = 0; mf < 4; mf++)
            #pragma unroll
            for (int nf = 0; nf < 4; nf++)
                mma_f16(acc[mf][nf], af[mf], (const uint32_t*)&bf[nf]);
    };

    int nk = K >> 4;
    ldg_tile(0);
    sts_tile(0);
    if (nk > 1) ldg_tile(16);
    __syncthreads();

    for (int kt = 0; kt < nk; kt++) {
        int st = kt & 1;
        compute(kt, st);
        if (kt + 1 < nk) {
            sts_tile(st ^ 1);
            if (kt + 2 < nk) ldg_tile((kt + 2) * 16);
        }
        __syncthreads();
    }

    #pragma unroll
    for (int mf = 0; mf < 4; mf++) {
        int rbase = m0 + wm * 64 + mf * 16 + grp;
        #pragma unroll
        for (int half = 0; half < 2; half++) {
            int row = rbase + half * 8;
            if (row >= M) continue;
            #pragma unroll
            for (int nf = 0; nf < 4; nf++) {
                int col = wn * 32 + nf * 8 + q * 2;
                float v0 = acc[mf][nf][half * 2 + 0];
                float v1 = acc[mf][nf][half * 2 + 1];
                if (bias) { v0 += bias[col]; v1 += bias[col + 1]; }
                if (ACT == 1) { v0 = lrelu(v0); v1 = lrelu(v1); }
                else if (ACT == 2) { v0 = fmaxf(v0, 0.f); v1 = fmaxf(v1, 0.f); }
                if (OUTHALF) {
                    __half* Ch = (__half*)Cv;
                    *(__half2*)&Ch[(size_t)row * ldc + col] = __floats2half2_rn(v0, v1);
                } else {
                    float* Cf = (float*)Cv;
                    Cf[(size_t)row * ldc + col]     = v0;
                    Cf[(size_t)row * ldc + col + 1] = v1;
                }
            }
        }
    }
}

// ---------------- L1: zero counters + prep all weights -----------------------
__global__ void k_L1(const float* __restrict__ des_w, const float* __restrict__ tweet_w,
                     const float* __restrict__ rel_w, const float* __restrict__ root_w,
                     const float* __restrict__ mlp_w1, uint32_t* __restrict__ bt) {
    int bid = blockIdx.x;
    if (bid < 391) {
        int i = bid * 256 + threadIdx.x;
        if (i < 2 * NN) g_cnt[i] = 0;
        if (i == 0) g_total = 0;
        return;
    }
    int pb = bid - 391;
    if (pb < 192)       dev_prep_b16(des_w,   bt + BT_DES, 768, pb);
    else if (pb < 384)  dev_prep_b16(tweet_w, bt + BT_TWE, 768, pb - 192);
    else if (pb < 512)  { int i = (pb - 384) >> 5;
                          dev_prep_b16(rel_w + (size_t)i * 16384, bt + BT_REL + i * 8192, 128, (pb - 384) & 31); }
    else if (pb < 576)  { int l = (pb - 512) >> 5;
                          dev_prep_b16(root_w + (size_t)l * 16384, bt + BT_ROOT + l * 8192, 128, (pb - 512) & 31); }
    else                dev_prep_b16(mlp_w1, bt + BT_MLP1, 128, pb - 576);
}

// ---------------- L2: des-GEMM ∥ tweets-GEMM ∥ hist ---------------------------
__global__ void __launch_bounds__(256, 2)
k_L2(const float* __restrict__ des, const float* __restrict__ tweets,
     const uint32_t* __restrict__ bt, const float* __restrict__ des_b,
     const float* __restrict__ tweet_b, __half* __restrict__ ox,
     __half* __restrict__ oh, const int* __restrict__ ei, const int* __restrict__ et) {
    __shared__ uint32_t As[2][1024];
    int bid = blockIdx.x;
    if (bid < 391)
        gemm_body16<1, false, true>(des, bt + BT_DES, des_b, ox, NN, 768, 128, bid, As);
    else if (bid < 782)
        gemm_body16<1, false, true>(tweets, bt + BT_TWE, tweet_b, oh, NN, 768, 128, bid - 391, As);
    else
        dev_hist(ei, et, bid - 782);
}

// ---------------- L3: combine (fp16 in/out) ∥ assign --------------------------
__global__ void k_L3(const float* __restrict__ numf, const float* __restrict__ catf,
                     const float* __restrict__ num_w, const float* __restrict__ num_b,
                     const float* __restrict__ cat_w, const float* __restrict__ cat_b,
                     const __half* __restrict__ gx, const __half* __restrict__ gh,
                     __half* __restrict__ px) {
    int bid = blockIdx.x;
    if (bid >= 6250) { dev_assign(bid - 6250); return; }
    int wid  = threadIdx.x >> 5;
    int lane = threadIdx.x & 31;
    int row  = bid * 8 + wid;
    if (row >= NN) return;

    float nv[5], cv[6];
    #pragma unroll
    for (int k = 0; k < 5; k++) nv[k] = numf[row * 5 + k];
    #pragma unroll
    for (int k = 0; k < 6; k++) cv[k] = catf[row * 6 + k];

    size_t base = (size_t)row * 128 + lane * 4;
    uint2 au = *(const uint2*)&gx[base];
    uint2 bu = *(const uint2*)&gh[base];
    float2 a01 = __half22float2(*(const __half2*)&au.x);
    float2 a23 = __half22float2(*(const __half2*)&au.y);
    float2 b01 = __half22float2(*(const __half2*)&bu.x);
    float2 b23 = __half22float2(*(const __half2*)&bu.y);
    float af[4] = {a01.x, a01.y, a23.x, a23.y};
    float bf[4] = {b01.x, b01.y, b23.x, b23.y};

    float o[4];
    #pragma unroll
    for (int u = 0; u < 4; u++) {
        int col = lane * 4 + u;
        float s = num_b[col];
        #pragma unroll
        for (int k = 0; k < 5; k++) s = fmaf(nv[k], num_w[k * 128 + col], s);
        float t = cat_b[col];
        #pragma unroll
        for (int k = 0; k < 6; k++) t = fmaf(cv[k], cat_w[k * 128 + col], t);
        o[u] = af[u] + bf[u] + lrelu(s) + lrelu(t);
    }
    __half2 h0 = __floats2half2_rn(o[0], o[1]);
    __half2 h1 = __floats2half2_rn(o[2], o[3]);
    *(uint2*)&px[base] = make_uint2(h2u(h0), h2u(h1));
}

// ---------------- RGCN multi-B GEMM: fp16 A resident, fp16 outputs ∥ fill ----
__global__ void __launch_bounds__(256, 2)
k_rgcn3(const __half* __restrict__ px,
        const uint32_t* __restrict__ b0p, const uint32_t* __restrict__ b1p,
        const uint32_t* __restrict__ b2p,
        __half* __restrict__ py, __half* __restrict__ proot,
        const int* __restrict__ ei, const int* __restrict__ et) {
    extern __shared__ uint32_t Asm[];
    int bid = blockIdx.x;
    if (bid >= 391) { dev_fill(ei, et, bid - 391); return; }

    int tid  = threadIdx.x;
    int lane = tid & 31;
    int w    = tid >> 5;
    int wm   = w & 1;
    int wn   = w >> 1;
    int m0   = bid * 128;
    int grp  = lane >> 2;
    int q    = lane & 3;

    #pragma unroll
    for (int kt = 0; kt < 8; kt++) {
        #pragma unroll
        for (int u = 0; u < 2; u++) {
            int unit = tid + u * 256;
            int row  = unit >> 2;
            int c4   = unit & 3;
            int ar   = m0 + row; if (ar >= NN) ar = NN - 1;
            uint2 ra = *(const uint2*)&px[(size_t)ar * 128 + kt * 16 + c4 * 4];
            *(uint2*)&Asm[kt * 1024 + a_off16(row, c4)] = ra;
        }
    }
    __syncthreads();

    const uint32_t* bsel[3] = { b0p, b1p, b2p };
    uint32_t sbase = smem_u32(Asm);
    uint32_t lro4  = ldsm_row_off(lane) * 4;

    #pragma unroll
    for (int b = 0; b < 3; b++) {
        const uint32_t* Bp = bsel[b];

        float acc[4][4][4];
        #pragma unroll
        for (int i = 0; i < 4; i++)
            #pragma unroll
            for (int j = 0; j < 4; j++)
                #pragma unroll
                for (int v = 0; v < 4; v++) acc[i][j][v] = 0.f;

        #pragma unroll
        for (int kt = 0; kt < 8; kt++) {
            const uint32_t* bbase = Bp + (size_t)kt * 1024;
            uint2 bf[4];
            #pragma unroll
            for (int nf = 0; nf < 4; nf++)
                bf[nf] = *(const uint2*)&bbase[(wn * 4 + nf) * 64 + lane * 2];
            uint32_t af[4][4];
            #pragma unroll
            for (int mf = 0; mf < 4; mf++)
                ldsm_x4(af[mf], sbase + (uint32_t)(kt * 1024 + (wm * 4 + mf) * 128) * 4 + lro4);
            #pragma unroll
            for (int mf = 0; mf < 4; mf++)
                #pragma unroll
                for (int nf = 0; nf < 4; nf++)
                    mma_f16(acc[mf][nf], af[mf], (const uint32_t*)&bf[nf]);
        }

        #pragma unroll
        for (int mf = 0; mf < 4; mf++) {
            int rbase = m0 + wm * 64 + mf * 16 + grp;
            #pragma unroll
            for (int half = 0; half < 2; half++) {
                int row = rbase + half * 8;
                if (row >= NN) continue;
                #pragma unroll
                for (int nf = 0; nf < 4; nf++) {
                    int col = wn * 32 + nf * 8 + q * 2;
                    __half2 hv = __floats2half2_rn(acc[mf][nf][half * 2 + 0],
                                                   acc[mf][nf][half * 2 + 1]);
                    if (b == 2)
                        *(__half2*)&proot[(size_t)row * 128 + col] = hv;
                    else
                        *(__half2*)&py[(size_t)row * 256 + b * 128 + col] = hv;
                }
            }
        }
    }
}

// ---------------- gather: scale-on-the-fly, 2x unrolled, lean addressing -----
__global__ void k_gather(const __half* __restrict__ y, const __half* __restrict__ root,
                         const float* __restrict__ bias, __half* __restrict__ xout) {
    int gw = (blockIdx.x * blockDim.x + threadIdx.x) >> 5;
    int lane = threadIdx.x & 31;
    if (gw >= NN) return;

    int beg = g_off[gw], len = g_len[gw];
    float i0 = g_inv[gw], i1 = g_inv[NN + gw];
    const char* yb = (const char*)y;
    uint32_t lo8 = (uint32_t)(lane * 8);

    float accA[4] = {0.f, 0.f, 0.f, 0.f};
    float accB[4] = {0.f, 0.f, 0.f, 0.f};

    int j = 0;
    for (; j + 2 <= len; j += 2) {
        int p0 = __ldg(&g_list[beg + j]);
        int p1 = __ldg(&g_list[beg + j + 1]);
        uint2 r0 = *(const uint2*)(yb + (((size_t)(uint32_t)p0) << 8) + lo8);
        uint2 r1 = *(const uint2*)(yb + (((size_t)(uint32_t)p1) << 8) + lo8);
        float s0 = (p0 & 1) ? i1 : i0;
        float s1 = (p1 & 1) ? i1 : i0;
        float2 f01 = __half22float2(*(const __half2*)&r0.x);
        float2 f23 = __half22float2(*(const __half2*)&r0.y);
        float2 g01 = __half22float2(*(const __half2*)&r1.x);
        float2 g23 = __half22float2(*(const __half2*)&r1.y);
        accA[0] = fmaf(f01.x, s0, accA[0]);
        accA[1] = fmaf(f01.y, s0, accA[1]);
        accA[2] = fmaf(f23.x, s0, accA[2]);
        accA[3] = fmaf(f23.y, s0, accA[3]);
        accB[0] = fmaf(g01.x, s1, accB[0]);
        accB[1] = fmaf(g01.y, s1, accB[1]);
        accB[2] = fmaf(g23.x, s1, accB[2]);
        accB[3] = fmaf(g23.y, s1, accB[3]);
    }
    if (j < len) {
        int p = __ldg(&g_list[beg + j]);
        uint2 r0 = *(const uint2*)(yb + (((size_t)(uint32_t)p) << 8) + lo8);
        float s = (p & 1) ? i1 : i0;
        float2 f01 = __half22float2(*(const __half2*)&r0.x);
        float2 f23 = __half22float2(*(const __half2*)&r0.y);
        accA[0] = fmaf(f01.x, s, accA[0]);
        accA[1] = fmaf(f01.y, s, accA[1]);
        accA[2] = fmaf(f23.x, s, accA[2]);
        accA[3] = fmaf(f23.y, s, accA[3]);
    }

    size_t base = (size_t)gw * 128 + lane * 4;
    uint2 ru = *(const uint2*)&root[base];
    float2 r01 = __half22float2(*(const __half2*)&ru.x);
    float2 r23 = __half22float2(*(const __half2*)&ru.y);
    float b0 = bias[lane * 4 + 0], b1 = bias[lane * 4 + 1];
    float b2 = bias[lane * 4 + 2], b3 = bias[lane * 4 + 3];

    float o0 = lrelu(r01.x + b0 + accA[0] + accB[0]);
    float o1 = lrelu(r01.y + b1 + accA[1] + accB[1]);
    float o2 = lrelu(r23.x + b2 + accA[2] + accB[2]);
    float o3 = lrelu(r23.y + b3 + accA[3] + accB[3]);
    __half2 h0 = __floats2half2_rn(o0, o1);
    __half2 h1 = __floats2half2_rn(o2, o3);
    *(uint2*)&xout[base] = make_uint2(h2u(h0), h2u(h1));
}

// ---------------- L8: MLP1 fp16 GEMM + fused 2-wide head ----------------------
__global__ void __launch_bounds__(256, 2)
k_mlp_head(const __half* __restrict__ A, const uint32_t* __restrict__ Bp,
           const float* __restrict__ b1, const float* __restrict__ w2,
           const float* __restrict__ b2, float* __restrict__ out) {
    __shared__ uint32_t As[2][1024];
    __shared__ float w2s[256];
    __shared__ float outs[128][2];

    int tid  = threadIdx.x;
    int lane = tid & 31;
    int w    = tid >> 5;
    int wm   = w & 1;
    int wn   = w >> 1;
    int m0   = blockIdx.x * 128;
    int grp  = lane >> 2;
    int q    = lane & 3;

    w2s[tid & 255] = w2[tid & 255];
    outs[tid >> 1][tid & 1] = 0.f;

    float acc[4][4][4];
    #pragma unroll
    for (int i = 0; i < 4; i++)
        #pragma unroll
        for (int j = 0; j < 4; j++)
            #pragma unroll
            for (int v = 0; v < 4; v++) acc[i][j][v] = 0.f;

    uint2 ra[2];
    const int K = 128;

    auto ldg_tile = [&](int kc) {
        #pragma unroll
        for (int u = 0; u < 2; u++) {
            int unit = tid + u * 256;
            int row  = unit >> 2;
            int c4   = unit & 3;
            int ar   = m0 + row; if (ar >= NN) ar = NN - 1;
            ra[u] = *(const uint2*)&A[(size_t)ar * K + kc + c4 * 4];
        }
    };
    auto sts_tile = [&](int st) {
        #pragma unroll
        for (int u = 0; u < 2; u++) {
            int unit = tid + u * 256;
            *(uint2*)&As[st][a_off16(unit >> 2, unit & 3)] = ra[u];
        }
    };
    uint32_t sbase = smem_u32(&As[0][0]);
    uint32_t lro4  = ldsm_row_off(lane) * 4;
    auto compute = [&](int kt, int st) {
        const uint32_t* bbase = Bp + (size_t)kt * 1024;
        uint2 bf[4];
        #pragma unroll
        for (int nf = 0; nf < 4; nf++)
            bf[nf] = *(const uint2*)&bbase[(wn * 4 + nf) * 64 + lane * 2];
        uint32_t af[4][4];
        #pragma unroll
        for (int mf = 0; mf < 4; mf++)
            ldsm_x4(af[mf], sbase + (uint32_t)(st * 1024 + (wm * 4 + mf) * 128) * 4 + lro4);
        #pragma unroll
        for (int mf = 0; mf < 4; mf++)
            #pragma unroll
            for (int nf = 0; nf < 4; nf++)
                mma_f16(acc[mf][nf], af[mf], (const uint32_t*)&bf[nf]);
    };

    int nk = K >> 4;   // 8
    ldg_tile(0);
    sts_tile(0);
    ldg_tile(16);
    __syncthreads();
    for (int kt = 0; kt < nk; kt++) {
        int st = kt & 1;
        compute(kt, st);
        if (kt + 1 < nk) {
            sts_tile(st ^ 1);
            if (kt + 2 < nk) ldg_tile((kt + 2) * 16);
        }
        __syncthreads();
    }

    // head: out[row] = relu(acc + b1) @ w2 + b2
    #pragma unroll
    for (int mf = 0; mf < 4; mf++) {
        #pragma unroll
        for (int half = 0; half < 2; half++) {
            int rl = wm * 64 + mf * 16 + grp + half * 8;
            float p0 = 0.f, p1 = 0.f;
            #pragma unroll
            for (int nf = 0; nf < 4; nf++) {
                #pragma unroll
                for (int v = 0; v < 2; v++) {
                    int col = wn * 32 + nf * 8 + q * 2 + v;
                    float h = fmaxf(acc[mf][nf][half * 2 + v] + b1[col], 0.f);
                    p0 = fmaf(h, w2s[col * 2 + 0], p0);
                    p1 = fmaf(h, w2s[col * 2 + 1], p1);
                }
            }
            p0 += __shfl_xor_sync(0xFFFFFFFFu, p0, 1);
            p0 += __shfl_xor_sync(0xFFFFFFFFu, p0, 2);
            p1 += __shfl_xor_sync(0xFFFFFFFFu, p1, 1);
            p1 += __shfl_xor_sync(0xFFFFFFFFu, p1, 2);
            if (q == 0) {
                atomicAdd(&outs[rl][0], p0);
                atomicAdd(&outs[rl][1], p1);
            }
        }
    }
    __syncthreads();
    int r = tid >> 1, c = tid & 1;
    int row = m0 + r;
    if (row < NN) out[row * 2 + c] = outs[r][c] + b2[c];
}

// ---------------- launch -------------------------------------------------------
#define RGCN_SMEM 32768

extern "C" void kernel_launch(void* const* d_in, const int* in_sizes, int n_in,
                              void* d_out, int out_size) {
    const float* des     = (const float*)d_in[0];
    const float* tweets  = (const float*)d_in[1];
    const float* numf    = (const float*)d_in[2];
    const float* catf    = (const float*)d_in[3];
    const int*   ei      = (const int*)d_in[4];
    const int*   et      = (const int*)d_in[5];
    const float* des_w   = (const float*)d_in[6];
    const float* des_b   = (const float*)d_in[7];
    const float* tweet_w = (const float*)d_in[8];
    const float* tweet_b = (const float*)d_in[9];
    const float* num_w   = (const float*)d_in[10];
    const float* num_b   = (const float*)d_in[11];
    const float* cat_w   = (const float*)d_in[12];
    const float* cat_b   = (const float*)d_in[13];
    const float* rel_w   = (const float*)d_in[14];
    const float* root_w  = (const float*)d_in[15];
    const float* rgcn_b  = (const float*)d_in[16];
    const float* mlp_w1  = (const float*)d_in[17];
    const float* mlp_b1  = (const float*)d_in[18];
    const float* mlp_w2  = (const float*)d_in[19];
    const float* mlp_b2  = (const float*)d_in[20];
    float* out = (float*)d_out;

    __half *px, *ph, *py, *proot;
    uint32_t *pbt;
    cudaGetSymbolAddress((void**)&px,    g_x);
    cudaGetSymbolAddress((void**)&ph,    g_h);
    cudaGetSymbolAddress((void**)&py,    g_y);
    cudaGetSymbolAddress((void**)&proot, g_root);
    cudaGetSymbolAddress((void**)&pbt,   g_bt);

    cudaFuncSetAttribute(k_rgcn3, cudaFuncAttributeMaxDynamicSharedMemorySize, RGCN_SMEM);

    // L1: zero counters ∥ prep all weights (fp16 frag order)
    k_L1<<<391 + 608, 256>>>(des_w, tweet_w, rel_w, root_w, mlp_w1, pbt);

    // L2: des-GEMM ∥ tweets-GEMM ∥ hist (fp16 outputs)
    k_L2<<<782 + 6250, 256>>>(des, tweets, pbt, des_b, tweet_b, px, ph, ei, et);

    // L3: combine (fp16) ∥ assign
    k_L3<<<6250 + 196, 256>>>(numf, catf, num_w, num_b, cat_w, cat_b, px, ph, px);

    // L4: RGCN layer 0 ∥ fill
    k_rgcn3<<<391 + 6250, 256, RGCN_SMEM>>>(px, pbt + BT_REL, pbt + BT_REL + 8192,
                                            pbt + BT_ROOT, py, proot, ei, et);
    k_gather<<<(NN * 32) / 256, 256>>>(py, proot, rgcn_b, px);

    // L6: RGCN layer 1
    k_rgcn3<<<391, 256, RGCN_SMEM>>>(px, pbt + BT_REL + 2 * 8192, pbt + BT_REL + 3 * 8192,
                                     pbt + BT_ROOT + 8192, py, proot, ei, et);
    k_gather<<<(NN * 32) / 256, 256>>>(py, proot, rgcn_b + 128, px);

    // L8: MLP1 + fused head
    k_mlp_head<<<391, 256>>>(px, pbt + BT_MLP1, mlp_b1, mlp_w2, mlp_b2, out);
}

// round 17
// speedup vs baseline: 1.1913x; 1.0454x over previous
#include <cuda_runtime.h>
#include <cuda_bf16.h>
#include <cuda_fp16.h>
#include <cstdint>

#define NN 50000
#define EE 1600000

// ---------------- scratch (device globals) ----------------------------------
__device__ __half g_x[NN * 128];     // node features fp16 (px)
__device__ __half g_h[NN * 128];     // tweets projection fp16
__device__ __half g_y[NN * 256];     // [Y0 | Y1] per node, fp16 messages
__device__ __half g_root[NN * 128];  // root projection fp16
__device__ uint32_t g_bt[155648];    // pre-packed fp16 weights (frag order)
__device__ int   g_cnt[2 * NN];
__device__ int   g_off[NN];
__device__ int   g_len[NN];
__device__ int   g_cur[NN];
__device__ int   g_list[EE];
__device__ float g_inv[2 * NN];
__device__ int   g_total;

// BT offsets in uint32 words (each word = half2)
#define BT_DES  0
#define BT_TWE  49152
#define BT_REL  98304         // + i*8192
#define BT_ROOT 131072        // + l*8192
#define BT_MLP1 147456

__device__ __forceinline__ float lrelu(float v) { return v > 0.f ? v : 0.01f * v; }

__device__ __forceinline__ uint32_t smem_u32(const void* p) {
    uint32_t a;
    asm("{ .reg .u64 t; cvta.to.shared.u64 t, %1; cvt.u32.u64 %0, t; }" : "=r"(a) : "l"(p));
    return a;
}

__device__ __forceinline__ void mma_f16(float c[4], const uint32_t a[4], const uint32_t b[2]) {
    asm volatile("mma.sync.aligned.m16n8k16.row.col.f32.f16.f16.f32 "
        "{%0,%1,%2,%3}, {%4,%5,%6,%7}, {%8,%9}, {%0,%1,%2,%3};"
        : "+f"(c[0]), "+f"(c[1]), "+f"(c[2]), "+f"(c[3])
        : "r"(a[0]), "r"(a[1]), "r"(a[2]), "r"(a[3]), "r"(b[0]), "r"(b[1]));
}

__device__ __forceinline__ void ldsm_x4(uint32_t r[4], uint32_t addr) {
    asm volatile("ldmatrix.sync.aligned.m8n8.x4.shared.b16 {%0,%1,%2,%3}, [%4];"
        : "=r"(r[0]), "=r"(r[1]), "=r"(r[2]), "=r"(r[3]) : "r"(addr));
}

__device__ __forceinline__ uint32_t h2u(__half2 h) { return *(uint32_t*)&h; }

// ---------------- device helpers ---------------------------------------------
__device__ __forceinline__ void dev_prep_b16(const float* __restrict__ src,
                                             uint32_t* __restrict__ dst, int K, int blk) {
    int w = blk * 256 + threadIdx.x;
    if (w >= K * 64) return;
    int kt = w >> 10;
    int within = w & 1023;
    int n8 = within >> 6;
    int rem = within & 63;
    int lane = rem >> 1;
    int j = rem & 1;
    int n = n8 * 8 + (lane >> 2);
    int k0 = kt * 16 + j * 8 + 2 * (lane & 3);
    __half2 h = __floats2half2_rn(src[(size_t)k0 * 128 + n], src[(size_t)(k0 + 1) * 128 + n]);
    dst[w] = h2u(h);
}

// hist: 4 edges per thread (independent RED chains)
__device__ __forceinline__ void dev_hist4(const int* __restrict__ ei,
                                          const int* __restrict__ et, int blk) {
    int base = blk * 1024 + threadIdx.x;
    #pragma unroll
    for (int u = 0; u < 4; u++) {
        int e = base + u * 256;
        if (e < EE) atomicAdd(&g_cnt[et[e] * NN + ei[EE + e]], 1);
    }
}

__device__ __forceinline__ void dev_assign(int blk) {
    int i = blk * 256 + threadIdx.x;
    if (i >= NN) return;
    int c0 = g_cnt[i], c1 = g_cnt[NN + i];
    int deg = c0 + c1;
    int pos = atomicAdd(&g_total, deg);
    g_off[i] = pos;
    g_cur[i] = pos;
    g_len[i] = deg;
    g_inv[i]      = 1.0f / (c0 > 0 ? (float)c0 : 1.0f);
    g_inv[NN + i] = 1.0f / (c1 > 0 ? (float)c1 : 1.0f);
}

// fill: 4 edges per thread, loads and atomics batched for MLP
__device__ __forceinline__ void dev_fill4(const int* __restrict__ ei,
                                          const int* __restrict__ et, int blk) {
    int base = blk * 1024 + threadIdx.x;
    int src[4], dst[4], rel[4], pos[4];
    bool ok[4];
    #pragma unroll
    for (int u = 0; u < 4; u++) {
        int e = base + u * 256;
        ok[u] = (e < EE);
        if (ok[u]) {
            src[u] = ei[e];
            dst[u] = ei[EE + e];
            rel[u] = et[e];
        }
    }
    #pragma unroll
    for (int u = 0; u < 4; u++)
        if (ok[u]) pos[u] = atomicAdd(&g_cur[dst[u]], 1);
    #pragma unroll
    for (int u = 0; u < 4; u++)
        if (ok[u]) g_list[pos[u]] = (src[u] << 1) | rel[u];
}

// A smem layout per ktile (1024 words): row r occupies words r*8..r*8+7;
// 16B chunk cc stored at position (cc ^ ((r>>2)&1)).
__device__ __forceinline__ uint32_t a_off16(int r, int c4) {
    return (uint32_t)(r * 8 + (((c4 >> 1) ^ ((r >> 2) & 1)) << 2) + (c4 & 1) * 2);
}

__device__ __forceinline__ uint32_t ldsm_row_off(int lane) {
    int r_local = (lane & 7) | (((lane >> 3) & 1) << 3);
    return (uint32_t)(r_local * 8 + ((((lane >> 4) & 1) ^ ((r_local >> 2) & 1)) << 2));
}

// ---------------- fp16 GEMM body ----------------------------------------------
template <int ACT, bool AHALF, bool OUTHALF>
__device__ __forceinline__ void gemm_body16(
    const void* __restrict__ Av, const uint32_t* __restrict__ Bp,
    const float* __restrict__ bias, void* __restrict__ Cv,
    int M, int K, int ldc, int bidx,
    uint32_t (*As)[1024]) {

    int tid  = threadIdx.x;
    int lane = tid & 31;
    int w    = tid >> 5;
    int wm   = w & 1;
    int wn   = w >> 1;
    int m0   = bidx * 128;
    int grp  = lane >> 2;
    int q    = lane & 3;

    float acc[4][4][4];
    #pragma unroll
    for (int i = 0; i < 4; i++)
        #pragma unroll
        for (int j = 0; j < 4; j++)
            #pragma unroll
            for (int v = 0; v < 4; v++) acc[i][j][v] = 0.f;

    uint4 ra4[2];
    uint2 ra2[2];

    auto ldg_tile = [&](int kc) {
        #pragma unroll
        for (int u = 0; u < 2; u++) {
            int unit = tid + u * 256;
            int row  = unit >> 2;
            int c4   = unit & 3;
            int ar   = m0 + row; if (ar >= M) ar = M - 1;
            if (AHALF) {
                const __half* Ah = (const __half*)Av;
                ra2[u] = *(const uint2*)&Ah[(size_t)ar * K + kc + c4 * 4];
            } else {
                const float* Af = (const float*)Av;
                ra4[u] = *(const uint4*)&Af[(size_t)ar * K + kc + c4 * 4];
            }
        }
    };

    auto sts_tile = [&](int st) {
        #pragma unroll
        for (int u = 0; u < 2; u++) {
            int unit = tid + u * 256;
            uint32_t off = a_off16(unit >> 2, unit & 3);
            if (AHALF) {
                *(uint2*)&As[st][off] = ra2[u];
            } else {
                const float* vf = (const float*)&ra4[u];
                __half2 h0 = __floats2half2_rn(vf[0], vf[1]);
                __half2 h1 = __floats2half2_rn(vf[2], vf[3]);
                *(uint2*)&As[st][off] = make_uint2(h2u(h0), h2u(h1));
            }
        }
    };

    uint32_t sbase = smem_u32(&As[0][0]);
    uint32_t lro4  = ldsm_row_off(lane) * 4;

    auto compute = [&](int kt, int st) {
        const uint32_t* bbase = Bp + (size_t)kt * 1024;
        uint2 bf[4];
        #pragma unroll
        for (int nf = 0; nf < 4; nf++)
            bf[nf] = *(const uint2*)&bbase[(wn * 4 + nf) * 64 + lane * 2];
        uint32_t af[4][4];
        #pragma unroll
        for (int mf = 0; mf < 4; mf++)
            ldsm_x4(af[mf], sbase + (uint32_t)(st * 1024 + (wm * 4 + mf) * 128) * 4 + lro4);
        #pragma unroll
        for (int mf = 0; mf < 4; mf++)
            #pragma unroll
            for (int nf = 0; nf < 4; nf++)
                mma_f16(acc[mf][nf], af[mf], (const uint32_t*)&bf[nf]);
    };

    int nk = K >> 4;
    ldg_tile(0);
    sts_tile(0);
    if (nk > 1) ldg_tile(16);
    __syncthreads();

    for (int kt = 0; kt < nk; kt++) {
        int st = kt & 1;
        compute(kt, st);
        if (kt + 1 < nk) {
            sts_tile(st ^ 1);
            if (kt + 2 < nk) ldg_tile((kt + 2) * 16);
        }
        __syncthreads();
    }

    #pragma unroll
    for (int mf = 0; mf < 4; mf++) {
        int rbase = m0 + wm * 64 + mf * 16 + grp;
        #pragma unroll
        for (int half = 0; half < 2; half++) {
            int row = rbase + half * 8;
            if (row >= M) continue;
            #pragma unroll
            for (int nf = 0; nf < 4; nf++) {
                int col = wn * 32 + nf * 8 + q * 2;
                float v0 = acc[mf][nf][half * 2 + 0];
                float v1 = acc[mf][nf][half * 2 + 1];
                if (bias) { v0 += bias[col]; v1 += bias[col + 1]; }
                if (ACT == 1) { v0 = lrelu(v0); v1 = lrelu(v1); }
                else if (ACT == 2) { v0 = fmaxf(v0, 0.f); v1 = fmaxf(v1, 0.f); }
                if (OUTHALF) {
                    __half* Ch = (__half*)Cv;
                    *(__half2*)&Ch[(size_t)row * ldc + col] = __floats2half2_rn(v0, v1);
                } else {
                    float* Cf = (float*)Cv;
                    Cf[(size_t)row * ldc + col]     = v0;
                    Cf[(size_t)row * ldc + col + 1] = v1;
                }
            }
        }
    }
}

// ---------------- L1: zero counters + prep all weights -----------------------
__global__ void k_L1(const float* __restrict__ des_w, const float* __restrict__ tweet_w,
                     const float* __restrict__ rel_w, const float* __restrict__ root_w,
                     const float* __restrict__ mlp_w1, uint32_t* __restrict__ bt) {
    int bid = blockIdx.x;
    if (bid < 391) {
        int i = bid * 256 + threadIdx.x;
        if (i < 2 * NN) g_cnt[i] = 0;
        if (i == 0) g_total = 0;
        return;
    }
    int pb = bid - 391;
    if (pb < 192)       dev_prep_b16(des_w,   bt + BT_DES, 768, pb);
    else if (pb < 384)  dev_prep_b16(tweet_w, bt + BT_TWE, 768, pb - 192);
    else if (pb < 512)  { int i = (pb - 384) >> 5;
                          dev_prep_b16(rel_w + (size_t)i * 16384, bt + BT_REL + i * 8192, 128, (pb - 384) & 31); }
    else if (pb < 576)  { int l = (pb - 512) >> 5;
                          dev_prep_b16(root_w + (size_t)l * 16384, bt + BT_ROOT + l * 8192, 128, (pb - 512) & 31); }
    else                dev_prep_b16(mlp_w1, bt + BT_MLP1, 128, pb - 576);
}

// ---------------- L2: des-GEMM ∥ tweets-GEMM ∥ hist(4x ILP) -------------------
__global__ void __launch_bounds__(256, 2)
k_L2(const float* __restrict__ des, const float* __restrict__ tweets,
     const uint32_t* __restrict__ bt, const float* __restrict__ des_b,
     const float* __restrict__ tweet_b, __half* __restrict__ ox,
     __half* __restrict__ oh, const int* __restrict__ ei, const int* __restrict__ et) {
    __shared__ uint32_t As[2][1024];
    int bid = blockIdx.x;
    if (bid < 391)
        gemm_body16<1, false, true>(des, bt + BT_DES, des_b, ox, NN, 768, 128, bid, As);
    else if (bid < 782)
        gemm_body16<1, false, true>(tweets, bt + BT_TWE, tweet_b, oh, NN, 768, 128, bid - 391, As);
    else
        dev_hist4(ei, et, bid - 782);
}

// ---------------- L3: combine (fp16 in/out) ∥ assign --------------------------
__global__ void k_L3(const float* __restrict__ numf, const float* __restrict__ catf,
                     const float* __restrict__ num_w, const float* __restrict__ num_b,
                     const float* __restrict__ cat_w, const float* __restrict__ cat_b,
                     const __half* __restrict__ gx, const __half* __restrict__ gh,
                     __half* __restrict__ px) {
    int bid = blockIdx.x;
    if (bid >= 6250) { dev_assign(bid - 6250); return; }
    int wid  = threadIdx.x >> 5;
    int lane = threadIdx.x & 31;
    int row  = bid * 8 + wid;
    if (row >= NN) return;

    float nv[5], cv[6];
    #pragma unroll
    for (int k = 0; k < 5; k++) nv[k] = numf[row * 5 + k];
    #pragma unroll
    for (int k = 0; k < 6; k++) cv[k] = catf[row * 6 + k];

    size_t base = (size_t)row * 128 + lane * 4;
    uint2 au = *(const uint2*)&gx[base];
    uint2 bu = *(const uint2*)&gh[base];
    float2 a01 = __half22float2(*(const __half2*)&au.x);
    float2 a23 = __half22float2(*(const __half2*)&au.y);
    float2 b01 = __half22float2(*(const __half2*)&bu.x);
    float2 b23 = __half22float2(*(const __half2*)&bu.y);
    float af[4] = {a01.x, a01.y, a23.x, a23.y};
    float bf[4] = {b01.x, b01.y, b23.x, b23.y};

    float o[4];
    #pragma unroll
    for (int u = 0; u < 4; u++) {
        int col = lane * 4 + u;
        float s = num_b[col];
        #pragma unroll
        for (int k = 0; k < 5; k++) s = fmaf(nv[k], num_w[k * 128 + col], s);
        float t = cat_b[col];
        #pragma unroll
        for (int k = 0; k < 6; k++) t = fmaf(cv[k], cat_w[k * 128 + col], t);
        o[u] = af[u] + bf[u] + lrelu(s) + lrelu(t);
    }
    __half2 h0 = __floats2half2_rn(o[0], o[1]);
    __half2 h1 = __floats2half2_rn(o[2], o[3]);
    *(uint2*)&px[base] = make_uint2(h2u(h0), h2u(h1));
}

// ---------------- RGCN multi-B GEMM ∥ fill(4x ILP) ----------------------------
__global__ void __launch_bounds__(256, 2)
k_rgcn3(const __half* __restrict__ px,
        const uint32_t* __restrict__ b0p, const uint32_t* __restrict__ b1p,
        const uint32_t* __restrict__ b2p,
        __half* __restrict__ py, __half* __restrict__ proot,
        const int* __restrict__ ei, const int* __restrict__ et) {
    extern __shared__ uint32_t Asm[];
    int bid = blockIdx.x;
    if (bid >= 391) { dev_fill4(ei, et, bid - 391); return; }

    int tid  = threadIdx.x;
    int lane = tid & 31;
    int w    = tid >> 5;
    int wm   = w & 1;
    int wn   = w >> 1;
    int m0   = bid * 128;
    int grp  = lane >> 2;
    int q    = lane & 3;

    #pragma unroll
    for (int kt = 0; kt < 8; kt++) {
        #pragma unroll
        for (int u = 0; u < 2; u++) {
            int unit = tid + u * 256;
            int row  = unit >> 2;
            int c4   = unit & 3;
            int ar   = m0 + row; if (ar >= NN) ar = NN - 1;
            uint2 ra = *(const uint2*)&px[(size_t)ar * 128 + kt * 16 + c4 * 4];
            *(uint2*)&Asm[kt * 1024 + a_off16(row, c4)] = ra;
        }
    }
    __syncthreads();

    const uint32_t* bsel[3] = { b0p, b1p, b2p };
    uint32_t sbase = smem_u32(Asm);
    uint32_t lro4  = ldsm_row_off(lane) * 4;

    #pragma unroll
    for (int b = 0; b < 3; b++) {
        const uint32_t* Bp = bsel[b];

        float acc[4][4][4];
        #pragma unroll
        for (int i = 0; i < 4; i++)
            #pragma unroll
            for (int j = 0; j < 4; j++)
                #pragma unroll
                for (int v = 0; v < 4; v++) acc[i][j][v] = 0.f;

        #pragma unroll
        for (int kt = 0; kt < 8; kt++) {
            const uint32_t* bbase = Bp + (size_t)kt * 1024;
            uint2 bf[4];
            #pragma unroll
            for (int nf = 0; nf < 4; nf++)
                bf[nf] = *(const uint2*)&bbase[(wn * 4 + nf) * 64 + lane * 2];
            uint32_t af[4][4];
            #pragma unroll
            for (int mf = 0; mf < 4; mf++)
                ldsm_x4(af[mf], sbase + (uint32_t)(kt * 1024 + (wm * 4 + mf) * 128) * 4 + lro4);
            #pragma unroll
            for (int mf = 0; mf < 4; mf++)
                #pragma unroll
                for (int nf = 0; nf < 4; nf++)
                    mma_f16(acc[mf][nf], af[mf], (const uint32_t*)&bf[nf]);
        }

        #pragma unroll
        for (int mf = 0; mf < 4; mf++) {
            int rbase = m0 + wm * 64 + mf * 16 + grp;
            #pragma unroll
            for (int half = 0; half < 2; half++) {
                int row = rbase + half * 8;
                if (row >= NN) continue;
                #pragma unroll
                for (int nf = 0; nf < 4; nf++) {
                    int col = wn * 32 + nf * 8 + q * 2;
                    __half2 hv = __floats2half2_rn(acc[mf][nf][half * 2 + 0],
                                                   acc[mf][nf][half * 2 + 1]);
                    if (b == 2)
                        *(__half2*)&proot[(size_t)row * 128 + col] = hv;
                    else
                        *(__half2*)&py[(size_t)row * 256 + b * 128 + col] = hv;
                }
            }
        }
    }
}

// ---------------- gather: scale-on-the-fly, 2x unrolled, lean addressing -----
__global__ void k_gather(const __half* __restrict__ y, const __half* __restrict__ root,
                         const float* __restrict__ bias, __half* __restrict__ xout) {
    int gw = (blockIdx.x * blockDim.x + threadIdx.x) >> 5;
    int lane = threadIdx.x & 31;
    if (gw >= NN) return;

    int beg = g_off[gw], len = g_len[gw];
    float i0 = g_inv[gw], i1 = g_inv[NN + gw];
    const char* yb = (const char*)y;
    uint32_t lo8 = (uint32_t)(lane * 8);

    float accA[4] = {0.f, 0.f, 0.f, 0.f};
    float accB[4] = {0.f, 0.f, 0.f, 0.f};

    int j = 0;
    for (; j + 2 <= len; j += 2) {
        int p0 = __ldg(&g_list[beg + j]);
        int p1 = __ldg(&g_list[beg + j + 1]);
        uint2 r0 = *(const uint2*)(yb + (((size_t)(uint32_t)p0) << 8) + lo8);
        uint2 r1 = *(const uint2*)(yb + (((size_t)(uint32_t)p1) << 8) + lo8);
        float s0 = (p0 & 1) ? i1 : i0;
        float s1 = (p1 & 1) ? i1 : i0;
        float2 f01 = __half22float2(*(const __half2*)&r0.x);
        float2 f23 = __half22float2(*(const __half2*)&r0.y);
        float2 g01 = __half22float2(*(const __half2*)&r1.x);
        float2 g23 = __half22float2(*(const __half2*)&r1.y);
        accA[0] = fmaf(f01.x, s0, accA[0]);
        accA[1] = fmaf(f01.y, s0, accA[1]);
        accA[2] = fmaf(f23.x, s0, accA[2]);
        accA[3] = fmaf(f23.y, s0, accA[3]);
        accB[0] = fmaf(g01.x, s1, accB[0]);
        accB[1] = fmaf(g01.y, s1, accB[1]);
        accB[2] = fmaf(g23.x, s1, accB[2]);
        accB[3] = fmaf(g23.y, s1, accB[3]);
    }
    if (j < len) {
        int p = __ldg(&g_list[beg + j]);
        uint2 r0 = *(const uint2*)(yb + (((size_t)(uint32_t)p) << 8) + lo8);
        float s = (p & 1) ? i1 : i0;
        float2 f01 = __half22float2(*(const __half2*)&r0.x);
        float2 f23 = __half22float2(*(const __half2*)&r0.y);
        accA[0] = fmaf(f01.x, s, accA[0]);
        accA[1] = fmaf(f01.y, s, accA[1]);
        accA[2] = fmaf(f23.x, s, accA[2]);
        accA[3] = fmaf(f23.y, s, accA[3]);
    }

    size_t base = (size_t)gw * 128 + lane * 4;
    uint2 ru = *(const uint2*)&root[base];
    float2 r01 = __half22float2(*(const __half2*)&ru.x);
    float2 r23 = __half22float2(*(const __half2*)&ru.y);
    float b0 = bias[lane * 4 + 0], b1 = bias[lane * 4 + 1];
    float b2 = bias[lane * 4 + 2], b3 = bias[lane * 4 + 3];

    float o0 = lrelu(r01.x + b0 + accA[0] + accB[0]);
    float o1 = lrelu(r01.y + b1 + accA[1] + accB[1]);
    float o2 = lrelu(r23.x + b2 + accA[2] + accB[2]);
    float o3 = lrelu(r23.y + b3 + accA[3] + accB[3]);
    __half2 h0 = __floats2half2_rn(o0, o1);
    __half2 h1 = __floats2half2_rn(o2, o3);
    *(uint2*)&xout[base] = make_uint2(h2u(h0), h2u(h1));
}

// ---------------- L8: MLP1 fp16 GEMM + fused 2-wide head ----------------------
__global__ void __launch_bounds__(256, 2)
k_mlp_head(const __half* __restrict__ A, const uint32_t* __restrict__ Bp,
           const float* __restrict__ b1, const float* __restrict__ w2,
           const float* __restrict__ b2, float* __restrict__ out) {
    __shared__ uint32_t As[2][1024];
    __shared__ float w2s[256];
    __shared__ float outs[128][2];

    int tid  = threadIdx.x;
    int lane = tid & 31;
    int w    = tid >> 5;
    int wm   = w & 1;
    int wn   = w >> 1;
    int m0   = blockIdx.x * 128;
    int grp  = lane >> 2;
    int q    = lane & 3;

    w2s[tid & 255] = w2[tid & 255];
    outs[tid >> 1][tid & 1] = 0.f;

    float acc[4][4][4];
    #pragma unroll
    for (int i = 0; i < 4; i++)
        #pragma unroll
        for (int j = 0; j < 4; j++)
            #pragma unroll
            for (int v = 0; v < 4; v++) acc[i][j][v] = 0.f;

    uint2 ra[2];
    const int K = 128;

    auto ldg_tile = [&](int kc) {
        #pragma unroll
        for (int u = 0; u < 2; u++) {
            int unit = tid + u * 256;
            int row  = unit >> 2;
            int c4   = unit & 3;
            int ar   = m0 + row; if (ar >= NN) ar = NN - 1;
            ra[u] = *(const uint2*)&A[(size_t)ar * K + kc + c4 * 4];
        }
    };
    auto sts_tile = [&](int st) {
        #pragma unroll
        for (int u = 0; u < 2; u++) {
            int unit = tid + u * 256;
            *(uint2*)&As[st][a_off16(unit >> 2, unit & 3)] = ra[u];
        }
    };
    uint32_t sbase = smem_u32(&As[0][0]);
    uint32_t lro4  = ldsm_row_off(lane) * 4;
    auto compute = [&](int kt, int st) {
        const uint32_t* bbase = Bp + (size_t)kt * 1024;
        uint2 bf[4];
        #pragma unroll
        for (int nf = 0; nf < 4; nf++)
            bf[nf] = *(const uint2*)&bbase[(wn * 4 + nf) * 64 + lane * 2];
        uint32_t af[4][4];
        #pragma unroll
        for (int mf = 0; mf < 4; mf++)
            ldsm_x4(af[mf], sbase + (uint32_t)(st * 1024 + (wm * 4 + mf) * 128) * 4 + lro4);
        #pragma unroll
        for (int mf = 0; mf < 4; mf++)
            #pragma unroll
            for (int nf = 0; nf < 4; nf++)
                mma_f16(acc[mf][nf], af[mf], (const uint32_t*)&bf[nf]);
    };

    int nk = K >> 4;   // 8
    ldg_tile(0);
    sts_tile(0);
    ldg_tile(16);
    __syncthreads();
    for (int kt = 0; kt < nk; kt++) {
        int st = kt & 1;
        compute(kt, st);
        if (kt + 1 < nk) {
            sts_tile(st ^ 1);
            if (kt + 2 < nk) ldg_tile((kt + 2) * 16);
        }
        __syncthreads();
    }

    // head: out[row] = relu(acc + b1) @ w2 + b2
    #pragma unroll
    for (int mf = 0; mf < 4; mf++) {
        #pragma unroll
        for (int half = 0; half < 2; half++) {
            int rl = wm * 64 + mf * 16 + grp + half * 8;
            float p0 = 0.f, p1 = 0.f;
            #pragma unroll
            for (int nf = 0; nf < 4; nf++) {
                #pragma unroll
                for (int v = 0; v < 2; v++) {
                    int col = wn * 32 + nf * 8 + q * 2 + v;
                    float h = fmaxf(acc[mf][nf][half * 2 + v] + b1[col], 0.f);
                    p0 = fmaf(h, w2s[col * 2 + 0], p0);
                    p1 = fmaf(h, w2s[col * 2 + 1], p1);
                }
            }
            p0 += __shfl_xor_sync(0xFFFFFFFFu, p0, 1);
            p0 += __shfl_xor_sync(0xFFFFFFFFu, p0, 2);
            p1 += __shfl_xor_sync(0xFFFFFFFFu, p1, 1);
            p1 += __shfl_xor_sync(0xFFFFFFFFu, p1, 2);
            if (q == 0) {
                atomicAdd(&outs[rl][0], p0);
                atomicAdd(&outs[rl][1], p1);
            }
        }
    }
    __syncthreads();
    int r = tid >> 1, c = tid & 1;
    int row = m0 + r;
    if (row < NN) out[row * 2 + c] = outs[r][c] + b2[c];
}

// ---------------- launch -------------------------------------------------------
#define RGCN_SMEM 32768

extern "C" void kernel_launch(void* const* d_in, const int* in_sizes, int n_in,
                              void* d_out, int out_size) {
    const float* des     = (const float*)d_in[0];
    const float* tweets  = (const float*)d_in[1];
    const float* numf    = (const float*)d_in[2];
    const float* catf    = (const float*)d_in[3];
    const int*   ei      = (const int*)d_in[4];
    const int*   et      = (const int*)d_in[5];
    const float* des_w   = (const float*)d_in[6];
    const float* des_b   = (const float*)d_in[7];
    const float* tweet_w = (const float*)d_in[8];
    const float* tweet_b = (const float*)d_in[9];
    const float* num_w   = (const float*)d_in[10];
    const float* num_b   = (const float*)d_in[11];
    const float* cat_w   = (const float*)d_in[12];
    const float* cat_b   = (const float*)d_in[13];
    const float* rel_w   = (const float*)d_in[14];
    const float* root_w  = (const float*)d_in[15];
    const float* rgcn_b  = (const float*)d_in[16];
    const float* mlp_w1  = (const float*)d_in[17];
    const float* mlp_b1  = (const float*)d_in[18];
    const float* mlp_w2  = (const float*)d_in[19];
    const float* mlp_b2  = (const float*)d_in[20];
    float* out = (float*)d_out;

    __half *px, *ph, *py, *proot;
    uint32_t *pbt;
    cudaGetSymbolAddress((void**)&px,    g_x);
    cudaGetSymbolAddress((void**)&ph,    g_h);
    cudaGetSymbolAddress((void**)&py,    g_y);
    cudaGetSymbolAddress((void**)&proot, g_root);
    cudaGetSymbolAddress((void**)&pbt,   g_bt);

    cudaFuncSetAttribute(k_rgcn3, cudaFuncAttributeMaxDynamicSharedMemorySize, RGCN_SMEM);

    // L1: zero counters ∥ prep all weights (fp16 frag order)
    k_L1<<<391 + 608, 256>>>(des_w, tweet_w, rel_w, root_w, mlp_w1, pbt);

    // L2: des-GEMM ∥ tweets-GEMM ∥ hist (4 edges/thread)
    k_L2<<<782 + 1563, 256>>>(des, tweets, pbt, des_b, tweet_b, px, ph, ei, et);

    // L3: combine (fp16) ∥ assign
    k_L3<<<6250 + 196, 256>>>(numf, catf, num_w, num_b, cat_w, cat_b, px, ph, px);

    // L4: RGCN layer 0 ∥ fill (4 edges/thread)
    k_rgcn3<<<391 + 1563, 256, RGCN_SMEM>>>(px, pbt + BT_REL, pbt + BT_REL + 8192,
                                            pbt + BT_ROOT, py, proot, ei, et);
    k_gather<<<(NN * 32) / 256, 256>>>(py, proot, rgcn_b, px);

    // L6: RGCN layer 1
    k_rgcn3<<<391, 256, RGCN_SMEM>>>(px, pbt + BT_REL + 2 * 8192, pbt + BT_REL + 3 * 8192,
                                     pbt + BT_ROOT + 8192, py, proot, ei, et);
    k_gather<<<(NN * 32) / 256, 256>>>(py, proot, rgcn_b + 128, px);

    // L8: MLP1 + fused head
    k_mlp_head<<<391, 256>>>(px, pbt + BT_MLP1, mlp_b1, mlp_w2, mlp_b2, out);
}